// round 1
// baseline (speedup 1.0000x reference)
#include <cuda_runtime.h>

#define NN 50000
#define KNBR 16

// ---------------- scratch (device globals; no runtime allocation) ----------------
__device__ float g_B1[128 * 128];            // [W_e1 | W_s1]
__device__ float g_B2[128 * 128];            // [W_e2 | W_s2]
__device__ float g_z[2 * NN * 128];          // layer1 out: cols 0:64 = xn, 64:128 = xs
__device__ float g_y[2 * NN * 128];          // layer2 out: cols 0:64 = yn, 64:128 = ys
__device__ float g_h[2 * NN * 128];          // sigmoid(cat(xs, aggr))
__device__ float g_aggr[2 * NN * 64];        // layer1 aggregates
__device__ float g_si[2 * NN];
__device__ float g_sj[2 * NN];
__device__ float g_nsq[2 * NN];              // ||aggr||^2
__device__ float g_norm[2 * NN * KNBR];      // final edge weights = cross_att * self_att

__device__ __forceinline__ float sigmoidf_(float x) { return 1.f / (1.f + __expf(-x)); }

// ---------------- pack [We|Ws] into 128x128 B matrices ----------------
__global__ void pack_B_kernel(const float* __restrict__ We1, const float* __restrict__ Ws1,
                              const float* __restrict__ We2, const float* __restrict__ Ws2) {
    int idx = blockIdx.x * blockDim.x + threadIdx.x;
    if (idx >= 128 * 128) return;
    int k = idx >> 7, j = idx & 127;
    g_B1[idx] = (j < 64) ? We1[k * 64 + j] : Ws1[k * 64 + (j - 64)];
    g_B2[idx] = (j < 64) ? We2[k * 64 + j] : Ws2[k * 64 + (j - 64)];
}

// ---------------- SGEMM: C[M,128] = A[M,128] @ B[128,128] ----------------
// BM=128, BN=128, BK=16, 256 threads, 8x8 per-thread register tile.
__global__ void gemm_rk(const float* __restrict__ Aext, int M, int layer, int rowOffC) {
    const float* __restrict__ A = (layer == 1) ? Aext : g_h;
    const float* __restrict__ B = (layer == 1) ? g_B1 : g_B2;
    float* __restrict__ C = (layer == 1) ? (g_z + (size_t)rowOffC * 128) : g_y;

    __shared__ float As[16][128];
    __shared__ float Bs[16][128];

    int tid = threadIdx.x;
    int tx = tid & 15, ty = tid >> 4;
    int rowBase = blockIdx.x * 128;

    float acc[8][8];
#pragma unroll
    for (int i = 0; i < 8; i++)
#pragma unroll
        for (int j = 0; j < 8; j++) acc[i][j] = 0.f;

    int ra = tid >> 1;            // A tile row this thread loads
    int ka = (tid & 1) * 8;       // A tile k-offset
    int rb = tid >> 4;            // B tile k-row
    int cb = (tid & 15) * 8;      // B tile col-offset

    for (int k0 = 0; k0 < 128; k0 += 16) {
        int rowA = rowBase + ra;
        float4 v0 = {0, 0, 0, 0}, v1 = {0, 0, 0, 0};
        if (rowA < M) {
            v0 = *(const float4*)(A + (size_t)rowA * 128 + k0 + ka);
            v1 = *(const float4*)(A + (size_t)rowA * 128 + k0 + ka + 4);
        }
        As[ka + 0][ra] = v0.x; As[ka + 1][ra] = v0.y; As[ka + 2][ra] = v0.z; As[ka + 3][ra] = v0.w;
        As[ka + 4][ra] = v1.x; As[ka + 5][ra] = v1.y; As[ka + 6][ra] = v1.z; As[ka + 7][ra] = v1.w;

        float4 b0 = *(const float4*)(B + (size_t)(k0 + rb) * 128 + cb);
        float4 b1 = *(const float4*)(B + (size_t)(k0 + rb) * 128 + cb + 4);
        *(float4*)&Bs[rb][cb] = b0;
        *(float4*)&Bs[rb][cb + 4] = b1;
        __syncthreads();

#pragma unroll
        for (int kk = 0; kk < 16; kk++) {
            float a[8], b[8];
#pragma unroll
            for (int i = 0; i < 8; i++) a[i] = As[kk][ty * 8 + i];
#pragma unroll
            for (int j = 0; j < 8; j++) b[j] = Bs[kk][tx * 8 + j];
#pragma unroll
            for (int i = 0; i < 8; i++)
#pragma unroll
                for (int j = 0; j < 8; j++) acc[i][j] += a[i] * b[j];
        }
        __syncthreads();
    }

#pragma unroll
    for (int i = 0; i < 8; i++) {
        int row = rowBase + ty * 8 + i;
        if (row < M) {
            float4 s0 = {acc[i][0], acc[i][1], acc[i][2], acc[i][3]};
            float4 s1 = {acc[i][4], acc[i][5], acc[i][6], acc[i][7]};
            *(float4*)(C + (size_t)row * 128 + tx * 8) = s0;
            *(float4*)(C + (size_t)row * 128 + tx * 8 + 4) = s1;
        }
    }
}

// ---------------- layer-1 aggregate + h + attention scalars ----------------
// 64 threads per node (thread = feature d), 4 nodes per 256-thread block.
__global__ void aggr_kernel(const int* __restrict__ nbr1, const int* __restrict__ nbr2,
                            const float* __restrict__ watt) {
    int t = threadIdx.x;
    int nodeLocal = t >> 6;
    int d = t & 63;
    int node = blockIdx.x * 4 + nodeLocal;   // grid = 2N/4, exact
    int g = node >= NN;
    int i = g ? node - NN : node;
    const int* nbr = g ? nbr2 : nbr1;
    size_t gbase = (size_t)g * NN;

    float s = 0.f;
#pragma unroll
    for (int k = 0; k < 16; k++) {
        int j = __ldg(&nbr[i * 16 + k]);
        s += __ldg(&g_z[(gbase + j) * 128 + d]);
    }
    s *= (1.f / 16.f);

    g_aggr[(size_t)node * 64 + d] = s;
    float xs = g_z[(size_t)node * 128 + 64 + d];
    g_h[(size_t)node * 128 + d] = sigmoidf_(xs);
    g_h[(size_t)node * 128 + 64 + d] = sigmoidf_(s);

    // three 64-wide dots: si = aggr.w[:64], sj = aggr.w[64:], nsq = ||aggr||^2
    float p0 = s * watt[d];
    float p1 = s * watt[64 + d];
    float p2 = s * s;
#pragma unroll
    for (int o = 16; o; o >>= 1) {
        p0 += __shfl_down_sync(0xffffffffu, p0, o);
        p1 += __shfl_down_sync(0xffffffffu, p1, o);
        p2 += __shfl_down_sync(0xffffffffu, p2, o);
    }
    __shared__ float red[3][8];
    int warp = t >> 5, lane = t & 31;
    if (lane == 0) { red[0][warp] = p0; red[1][warp] = p1; red[2][warp] = p2; }
    __syncthreads();
    if (d == 0) {
        g_si[node]  = red[0][nodeLocal * 2] + red[0][nodeLocal * 2 + 1];
        g_sj[node]  = red[1][nodeLocal * 2] + red[1][nodeLocal * 2 + 1];
        g_nsq[node] = red[2][nodeLocal * 2] + red[2][nodeLocal * 2 + 1];
    }
}

// ---------------- cross-attn + self-attn -> final edge weights ----------------
// One warp per node; 4 warps (128 threads) per block. grid = N/4 (exact).
// Per warp: a1 (16x64), a2 (16x64) in smem; sim 16x16 via 2x4 register tiles.
__global__ void attn_kernel(const int* __restrict__ nbr1, const int* __restrict__ nbr2) {
    __shared__ float sm[4][2 * 1024 + 16 * 17];   // a1 | a2 | sims (padded rows)
    int warp = threadIdx.x >> 5;
    int lane = threadIdx.x & 31;
    int i = blockIdx.x * 4 + warp;
    float* a1s = sm[warp];
    float* a2s = sm[warp] + 1024;
    float* sims = sm[warp] + 2048;

    int nid;
    if (lane < 16) nid = nbr1[i * 16 + lane];
    else           nid = nbr2[i * 16 + (lane - 16)];

#pragma unroll 4
    for (int it = 0; it < 32; it++) {
        int idx = it * 32 + lane;
        int row = idx >> 6, d = idx & 63;
        int j1 = __shfl_sync(0xffffffffu, nid, row);
        int j2 = __shfl_sync(0xffffffffu, nid, 16 + row);
        a1s[idx] = g_aggr[(size_t)j1 * 64 + d];
        a2s[idx] = g_aggr[(size_t)(NN + j2) * 64 + d];
    }
    float myNsq = (lane < 16) ? g_nsq[nid] : g_nsq[NN + nid];
    __syncwarp();

    // lane -> (kg in [0,8): rows kg*2+{0,1}) x (lg in [0,4): cols lg*4+{0..3})
    int kg = lane >> 2;
    int lg = lane & 3;
    float acc0[4] = {0, 0, 0, 0};
    float acc1[4] = {0, 0, 0, 0};
    const float4* A1 = (const float4*)a1s;
    const float4* A2 = (const float4*)a2s;
#pragma unroll
    for (int d4 = 0; d4 < 16; d4++) {
        float4 a0 = A1[(kg * 2 + 0) * 16 + d4];
        float4 a1 = A1[(kg * 2 + 1) * 16 + d4];
#pragma unroll
        for (int t = 0; t < 4; t++) {
            float4 b = A2[(lg * 4 + t) * 16 + d4];
            acc0[t] += a0.x * b.x + a0.y * b.y + a0.z * b.z + a0.w * b.w;
            acc1[t] += a1.x * b.x + a1.y * b.y + a1.z * b.z + a1.w * b.w;
        }
    }
    float nsqK0 = __shfl_sync(0xffffffffu, myNsq, kg * 2);
    float nsqK1 = __shfl_sync(0xffffffffu, myNsq, kg * 2 + 1);
#pragma unroll
    for (int t = 0; t < 4; t++) {
        int l = lg * 4 + t;
        float nsqL = __shfl_sync(0xffffffffu, myNsq, 16 + l);
        float d20 = nsqK0 + nsqL - 2.f * acc0[t];
        float d21 = nsqK1 + nsqL - 2.f * acc1[t];
        sims[(kg * 2 + 0) * 17 + l] = __expf(-sqrtf(fmaxf(d20, 1e-12f)));
        sims[(kg * 2 + 1) * 17 + l] = __expf(-sqrtf(fmaxf(d21, 1e-12f)));
    }
    __syncwarp();

    // lanes 0..15: row sums (att1); lanes 16..31: col sums (att2)
    float half;
    if (lane < 16) {
        float s = 0;
#pragma unroll
        for (int l = 0; l < 16; l++) s += sims[lane * 17 + l];
        half = s;
    } else {
        int l = lane - 16;
        float s = 0;
#pragma unroll
        for (int k = 0; k < 16; k++) s += sims[k * 17 + l];
        half = s;
    }
    float tot = half;                           // both 16-lane groups sum to grand total
#pragma unroll
    for (int o = 8; o; o >>= 1) tot += __shfl_xor_sync(0xffffffffu, tot, o);

    // self-attention softmax per graph half
    float sii = (lane < 16) ? g_si[i] : g_si[NN + i];
    float sjv = (lane < 16) ? g_sj[nid] : g_sj[NN + nid];
    float zz = sii + sjv;
    float lr = (zz >= 0.f) ? zz : 0.01f * zz;
    float e = __expf(lr);
    float esum = e;
#pragma unroll
    for (int o = 8; o; o >>= 1) esum += __shfl_xor_sync(0xffffffffu, esum, o);

    float nrm = (half / tot) * (e / esum);
    if (lane < 16) g_norm[(size_t)i * 16 + lane] = nrm;
    else           g_norm[(size_t)(NN + i) * 16 + (lane - 16)] = nrm;
}

// ---------------- final weighted aggregate + sigmoid -> output ----------------
__global__ void out_kernel(const int* __restrict__ nbr1, const int* __restrict__ nbr2,
                           float* __restrict__ out) {
    int t = threadIdx.x;
    int nodeLocal = t >> 6;
    int d = t & 63;
    int node = blockIdx.x * 4 + nodeLocal;
    int g = node >= NN;
    int i = g ? node - NN : node;
    const int* nbr = g ? nbr2 : nbr1;
    size_t gbase = (size_t)g * NN;

    float s = 0.f;
#pragma unroll
    for (int k = 0; k < 16; k++) {
        int j = __ldg(&nbr[i * 16 + k]);
        float w = g_norm[(size_t)node * 16 + k];
        s += w * __ldg(&g_y[(gbase + j) * 128 + d]);
    }
    float ys = g_y[(size_t)node * 128 + 64 + d];
    out[(size_t)node * 128 + d] = sigmoidf_(ys);
    out[(size_t)node * 128 + 64 + d] = sigmoidf_(s);
}

// ---------------- launch ----------------
extern "C" void kernel_launch(void* const* d_in, const int* in_sizes, int n_in,
                              void* d_out, int out_size) {
    const float* x1   = (const float*)d_in[0];
    const float* x2   = (const float*)d_in[1];
    const int*   nbr1 = (const int*)d_in[2];
    const int*   nbr2 = (const int*)d_in[3];
    const float* We1  = (const float*)d_in[4];
    const float* Ws1  = (const float*)d_in[5];
    const float* We2  = (const float*)d_in[6];
    const float* Ws2  = (const float*)d_in[7];
    const float* watt = (const float*)d_in[8];
    float* out = (float*)d_out;

    pack_B_kernel<<<64, 256>>>(We1, Ws1, We2, Ws2);

    int gb1 = (NN + 127) / 128;
    gemm_rk<<<gb1, 256>>>(x1, NN, 1, 0);
    gemm_rk<<<gb1, 256>>>(x2, NN, 1, NN);

    aggr_kernel<<<(2 * NN) / 4, 256>>>(nbr1, nbr2, watt);
    attn_kernel<<<NN / 4, 128>>>(nbr1, nbr2);

    gemm_rk<<<(2 * NN + 127) / 128, 256>>>(nullptr, 2 * NN, 2, 0);

    out_kernel<<<(2 * NN) / 4, 256>>>(nbr1, nbr2, out);
}

// round 2
// speedup vs baseline: 1.3440x; 1.3440x over previous
#include <cuda_runtime.h>
#include <cstdint>

#define NN 50000
#define KNBR 16

// ---------------- scratch (device globals; no runtime allocation) ----------------
__device__ float g_B1[128 * 128];            // [W_e1 | W_s1], tf32-rounded
__device__ float g_B2[128 * 128];            // [W_e2 | W_s2], tf32-rounded
__device__ float g_z[2 * NN * 128];          // layer1 out: cols 0:64 = xn, 64:128 = xs
__device__ float g_y[2 * NN * 128];          // layer2 out: cols 0:64 = yn, 64:128 = ys
__device__ float g_h[2 * NN * 128];          // sigmoid(cat(xs, aggr))
__device__ float g_aggr[2 * NN * 64];        // layer1 aggregates
__device__ float g_si[2 * NN];
__device__ float g_sj[2 * NN];
__device__ float g_nsq[2 * NN];              // ||aggr||^2
__device__ float g_norm[2 * NN * KNBR];      // final edge weights = cross_att * self_att

__device__ __forceinline__ float sigmoidf_(float x) { return 1.f / (1.f + __expf(-x)); }
__device__ __forceinline__ float tf32r(float x) {
    float r; asm("cvt.rna.tf32.f32 %0, %1;" : "=f"(r) : "f"(x)); return r;
}

// ---------------- pack [We|Ws] into 128x128 B matrices (tf32-rounded) ----------------
__global__ void pack_B_kernel(const float* __restrict__ We1, const float* __restrict__ Ws1,
                              const float* __restrict__ We2, const float* __restrict__ Ws2) {
    int idx = blockIdx.x * blockDim.x + threadIdx.x;
    if (idx >= 128 * 128) return;
    int k = idx >> 7, j = idx & 127;
    g_B1[idx] = tf32r((j < 64) ? We1[k * 64 + j] : Ws1[k * 64 + (j - 64)]);
    g_B2[idx] = tf32r((j < 64) ? We2[k * 64 + j] : Ws2[k * 64 + (j - 64)]);
}

// ---------------- TF32 tensor-core GEMM: C[M,128] = A[M,128] @ B[128,128] ----------------
// 256 threads = 8 warps (4m x 2n). Block tile 128x128, full K=128 resident in smem.
// As stride 132 (bank = 4*row + k, conflict-free), Bs[k][n] stride 136 (bank = 8*k + n).
#define AS_STRIDE 132
#define BS_STRIDE 136
#define GEMM_SMEM ((128 * AS_STRIDE + 128 * BS_STRIDE) * 4)

__device__ __forceinline__ void mma_tf32(float* d, const uint32_t* a, uint32_t b0, uint32_t b1) {
    asm volatile(
        "mma.sync.aligned.m16n8k8.row.col.f32.tf32.tf32.f32 "
        "{%0,%1,%2,%3}, {%4,%5,%6,%7}, {%8,%9}, {%0,%1,%2,%3};"
        : "+f"(d[0]), "+f"(d[1]), "+f"(d[2]), "+f"(d[3])
        : "r"(a[0]), "r"(a[1]), "r"(a[2]), "r"(a[3]), "r"(b0), "r"(b1));
}

__global__ void gemm_tc(const float* __restrict__ x1, const float* __restrict__ x2, int layer) {
    extern __shared__ float sm[];
    float* As = sm;                       // [128][AS_STRIDE]
    float* Bs = sm + 128 * AS_STRIDE;     // [128][BS_STRIDE]

    const int Mtot = 2 * NN;
    const float* __restrict__ Bg = (layer == 1) ? g_B1 : g_B2;
    float* __restrict__ C = (layer == 1) ? g_z : g_y;

    int tid = threadIdx.x;
    int rowBase = blockIdx.x * 128;

    // ---- load A tile (tf32-round) ----
#pragma unroll
    for (int it = 0; it < 16; it++) {
        int row = (tid >> 5) + it * 8;
        int k4 = (tid & 31) * 4;
        int grow = rowBase + row;
        float4 v = {0.f, 0.f, 0.f, 0.f};
        if (grow < Mtot) {
            const float* src;
            if (layer == 1)
                src = (grow < NN) ? (x1 + (size_t)grow * 128) : (x2 + (size_t)(grow - NN) * 128);
            else
                src = g_h + (size_t)grow * 128;
            v = *(const float4*)(src + k4);
        }
        float4 c = {tf32r(v.x), tf32r(v.y), tf32r(v.z), tf32r(v.w)};
        *(float4*)&As[row * AS_STRIDE + k4] = c;
    }
    // ---- load B tile (already tf32-rounded) ----
#pragma unroll
    for (int it = 0; it < 16; it++) {
        int k = (tid >> 5) + it * 8;
        int n4 = (tid & 31) * 4;
        float4 v = *(const float4*)(Bg + k * 128 + n4);
        *(float4*)&Bs[k * BS_STRIDE + n4] = v;
    }
    __syncthreads();

    // ---- compute ----
    int lane = tid & 31;
    int wm = (tid >> 5) & 3;
    int wn = tid >> 7;
    int rA = wm * 32 + (lane >> 2);
    int kq = lane & 3;
    int nB = wn * 64 + (lane >> 2);

    float acc[2][8][4];
#pragma unroll
    for (int mf = 0; mf < 2; mf++)
#pragma unroll
        for (int nf = 0; nf < 8; nf++)
#pragma unroll
            for (int c = 0; c < 4; c++) acc[mf][nf][c] = 0.f;

#pragma unroll
    for (int ks = 0; ks < 16; ks++) {
        int kb = ks * 8;
        uint32_t a[2][4];
#pragma unroll
        for (int mf = 0; mf < 2; mf++) {
            int r = rA + mf * 16;
            a[mf][0] = __float_as_uint(As[r * AS_STRIDE + kb + kq]);
            a[mf][1] = __float_as_uint(As[(r + 8) * AS_STRIDE + kb + kq]);
            a[mf][2] = __float_as_uint(As[r * AS_STRIDE + kb + kq + 4]);
            a[mf][3] = __float_as_uint(As[(r + 8) * AS_STRIDE + kb + kq + 4]);
        }
#pragma unroll
        for (int nf = 0; nf < 8; nf++) {
            uint32_t b0 = __float_as_uint(Bs[(kb + kq) * BS_STRIDE + nB + nf * 8]);
            uint32_t b1 = __float_as_uint(Bs[(kb + kq + 4) * BS_STRIDE + nB + nf * 8]);
            mma_tf32(acc[0][nf], a[0], b0, b1);
            mma_tf32(acc[1][nf], a[1], b0, b1);
        }
    }

    // ---- store C ----
#pragma unroll
    for (int mf = 0; mf < 2; mf++) {
#pragma unroll
        for (int nf = 0; nf < 8; nf++) {
            int row = rowBase + wm * 32 + mf * 16 + (lane >> 2);
            int col = wn * 64 + nf * 8 + (lane & 3) * 2;
            if (row < Mtot) {
                float2 v0 = {acc[mf][nf][0], acc[mf][nf][1]};
                *(float2*)&C[(size_t)row * 128 + col] = v0;
            }
            if (row + 8 < Mtot) {
                float2 v1 = {acc[mf][nf][2], acc[mf][nf][3]};
                *(float2*)&C[(size_t)(row + 8) * 128 + col] = v1;
            }
        }
    }
}

// ---------------- layer-1 aggregate + h + attention scalars ----------------
// 16 threads per node (thread = 4 features), 16 nodes per 256-thread block.
__global__ void aggr_kernel(const int* __restrict__ nbr1, const int* __restrict__ nbr2,
                            const float* __restrict__ watt) {
    int t = threadIdx.x;
    int nodeLocal = t >> 4;
    int q = t & 15;                       // feature quad: features q*4 .. q*4+3
    int node = blockIdx.x * 16 + nodeLocal;  // grid = 2N/16, exact
    int g = node >= NN;
    int i = g ? node - NN : node;
    const int* nbr = g ? nbr2 : nbr1;
    size_t gbase = (size_t)g * NN;

    int nid = __ldg(&nbr[i * 16 + q]);    // lane q holds neighbor q

    float4 s = {0.f, 0.f, 0.f, 0.f};
#pragma unroll
    for (int k = 0; k < 16; k++) {
        int j = __shfl_sync(0xffffffffu, nid, k, 16);
        float4 v = *(const float4*)&g_z[(gbase + j) * 128 + q * 4];
        s.x += v.x; s.y += v.y; s.z += v.z; s.w += v.w;
    }
    s.x *= (1.f / 16.f); s.y *= (1.f / 16.f); s.z *= (1.f / 16.f); s.w *= (1.f / 16.f);

    *(float4*)&g_aggr[(size_t)node * 64 + q * 4] = s;

    float4 xs = *(const float4*)&g_z[(size_t)node * 128 + 64 + q * 4];
    float4 hx = {sigmoidf_(xs.x), sigmoidf_(xs.y), sigmoidf_(xs.z), sigmoidf_(xs.w)};
    float4 ha = {sigmoidf_(s.x), sigmoidf_(s.y), sigmoidf_(s.z), sigmoidf_(s.w)};
    *(float4*)&g_h[(size_t)node * 128 + q * 4] = hx;
    *(float4*)&g_h[(size_t)node * 128 + 64 + q * 4] = ha;

    // three 64-wide dots over the 16-lane group
    float4 w0 = *(const float4*)&watt[q * 4];
    float4 w1 = *(const float4*)&watt[64 + q * 4];
    float p0 = s.x * w0.x + s.y * w0.y + s.z * w0.z + s.w * w0.w;
    float p1 = s.x * w1.x + s.y * w1.y + s.z * w1.z + s.w * w1.w;
    float p2 = s.x * s.x + s.y * s.y + s.z * s.z + s.w * s.w;
#pragma unroll
    for (int o = 8; o; o >>= 1) {
        p0 += __shfl_xor_sync(0xffffffffu, p0, o);
        p1 += __shfl_xor_sync(0xffffffffu, p1, o);
        p2 += __shfl_xor_sync(0xffffffffu, p2, o);
    }
    if (q == 0) {
        g_si[node] = p0;
        g_sj[node] = p1;
        g_nsq[node] = p2;
    }
}

// ---------------- cross-attn + self-attn -> final edge weights ----------------
// One warp per node; 4 warps (128 threads) per block. grid = N/4 (exact).
__global__ void attn_kernel(const int* __restrict__ nbr1, const int* __restrict__ nbr2) {
    __shared__ float sm[4][2 * 1024 + 16 * 17];   // a1 | a2 | sims (padded rows)
    int warp = threadIdx.x >> 5;
    int lane = threadIdx.x & 31;
    int i = blockIdx.x * 4 + warp;
    float* a1s = sm[warp];
    float* a2s = sm[warp] + 1024;
    float* sims = sm[warp] + 2048;

    int nid;
    if (lane < 16) nid = nbr1[i * 16 + lane];
    else           nid = nbr2[i * 16 + (lane - 16)];

#pragma unroll 4
    for (int it = 0; it < 32; it++) {
        int idx = it * 32 + lane;
        int row = idx >> 6, d = idx & 63;
        int j1 = __shfl_sync(0xffffffffu, nid, row);
        int j2 = __shfl_sync(0xffffffffu, nid, 16 + row);
        a1s[idx] = g_aggr[(size_t)j1 * 64 + d];
        a2s[idx] = g_aggr[(size_t)(NN + j2) * 64 + d];
    }
    float myNsq = (lane < 16) ? g_nsq[nid] : g_nsq[NN + nid];
    __syncwarp();

    int kg = lane >> 2;
    int lg = lane & 3;
    float acc0[4] = {0, 0, 0, 0};
    float acc1[4] = {0, 0, 0, 0};
    const float4* A1 = (const float4*)a1s;
    const float4* A2 = (const float4*)a2s;
#pragma unroll
    for (int d4 = 0; d4 < 16; d4++) {
        float4 a0 = A1[(kg * 2 + 0) * 16 + d4];
        float4 a1 = A1[(kg * 2 + 1) * 16 + d4];
#pragma unroll
        for (int t = 0; t < 4; t++) {
            float4 b = A2[(lg * 4 + t) * 16 + d4];
            acc0[t] += a0.x * b.x + a0.y * b.y + a0.z * b.z + a0.w * b.w;
            acc1[t] += a1.x * b.x + a1.y * b.y + a1.z * b.z + a1.w * b.w;
        }
    }
    float nsqK0 = __shfl_sync(0xffffffffu, myNsq, kg * 2);
    float nsqK1 = __shfl_sync(0xffffffffu, myNsq, kg * 2 + 1);
#pragma unroll
    for (int t = 0; t < 4; t++) {
        int l = lg * 4 + t;
        float nsqL = __shfl_sync(0xffffffffu, myNsq, 16 + l);
        float d20 = nsqK0 + nsqL - 2.f * acc0[t];
        float d21 = nsqK1 + nsqL - 2.f * acc1[t];
        sims[(kg * 2 + 0) * 17 + l] = __expf(-sqrtf(fmaxf(d20, 1e-12f)));
        sims[(kg * 2 + 1) * 17 + l] = __expf(-sqrtf(fmaxf(d21, 1e-12f)));
    }
    __syncwarp();

    float half;
    if (lane < 16) {
        float s = 0;
#pragma unroll
        for (int l = 0; l < 16; l++) s += sims[lane * 17 + l];
        half = s;
    } else {
        int l = lane - 16;
        float s = 0;
#pragma unroll
        for (int k = 0; k < 16; k++) s += sims[k * 17 + l];
        half = s;
    }
    float tot = half;
#pragma unroll
    for (int o = 8; o; o >>= 1) tot += __shfl_xor_sync(0xffffffffu, tot, o);

    float sii = (lane < 16) ? g_si[i] : g_si[NN + i];
    float sjv = (lane < 16) ? g_sj[nid] : g_sj[NN + nid];
    float zz = sii + sjv;
    float lr = (zz >= 0.f) ? zz : 0.01f * zz;
    float e = __expf(lr);
    float esum = e;
#pragma unroll
    for (int o = 8; o; o >>= 1) esum += __shfl_xor_sync(0xffffffffu, esum, o);

    float nrm = (half / tot) * (e / esum);
    if (lane < 16) g_norm[(size_t)i * 16 + lane] = nrm;
    else           g_norm[(size_t)(NN + i) * 16 + (lane - 16)] = nrm;
}

// ---------------- final weighted aggregate + sigmoid -> output ----------------
// 16 threads per node (float4 per thread), 16 nodes per block.
__global__ void out_kernel(const int* __restrict__ nbr1, const int* __restrict__ nbr2,
                           float* __restrict__ out) {
    int t = threadIdx.x;
    int nodeLocal = t >> 4;
    int q = t & 15;
    int node = blockIdx.x * 16 + nodeLocal;
    int g = node >= NN;
    int i = g ? node - NN : node;
    const int* nbr = g ? nbr2 : nbr1;
    size_t gbase = (size_t)g * NN;

    int nid = __ldg(&nbr[i * 16 + q]);
    float wq = g_norm[(size_t)node * 16 + q];

    float4 s = {0.f, 0.f, 0.f, 0.f};
#pragma unroll
    for (int k = 0; k < 16; k++) {
        int j = __shfl_sync(0xffffffffu, nid, k, 16);
        float w = __shfl_sync(0xffffffffu, wq, k, 16);
        float4 v = *(const float4*)&g_y[(gbase + j) * 128 + q * 4];
        s.x += w * v.x; s.y += w * v.y; s.z += w * v.z; s.w += w * v.w;
    }

    float4 ys = *(const float4*)&g_y[(size_t)node * 128 + 64 + q * 4];
    float4 o0 = {sigmoidf_(ys.x), sigmoidf_(ys.y), sigmoidf_(ys.z), sigmoidf_(ys.w)};
    float4 o1 = {sigmoidf_(s.x), sigmoidf_(s.y), sigmoidf_(s.z), sigmoidf_(s.w)};
    *(float4*)&out[(size_t)node * 128 + q * 4] = o0;
    *(float4*)&out[(size_t)node * 128 + 64 + q * 4] = o1;
}

// ---------------- launch ----------------
extern "C" void kernel_launch(void* const* d_in, const int* in_sizes, int n_in,
                              void* d_out, int out_size) {
    const float* x1   = (const float*)d_in[0];
    const float* x2   = (const float*)d_in[1];
    const int*   nbr1 = (const int*)d_in[2];
    const int*   nbr2 = (const int*)d_in[3];
    const float* We1  = (const float*)d_in[4];
    const float* Ws1  = (const float*)d_in[5];
    const float* We2  = (const float*)d_in[6];
    const float* Ws2  = (const float*)d_in[7];
    const float* watt = (const float*)d_in[8];
    float* out = (float*)d_out;

    cudaFuncSetAttribute(gemm_tc, cudaFuncAttributeMaxDynamicSharedMemorySize, GEMM_SMEM);

    pack_B_kernel<<<64, 256>>>(We1, Ws1, We2, Ws2);

    int gb = (2 * NN + 127) / 128;   // 782
    gemm_tc<<<gb, 256, GEMM_SMEM>>>(x1, x2, 1);

    aggr_kernel<<<(2 * NN) / 16, 256>>>(nbr1, nbr2, watt);
    attn_kernel<<<NN / 4, 128>>>(nbr1, nbr2);

    gemm_tc<<<gb, 256, GEMM_SMEM>>>(x1, x2, 2);

    out_kernel<<<(2 * NN) / 16, 256>>>(nbr1, nbr2, out);
}

// round 3
// speedup vs baseline: 2.1366x; 1.5897x over previous
#include <cuda_runtime.h>
#include <cstdint>

#define NN 50000
#define KNBR 16

// ---------------- scratch (device globals; no runtime allocation) ----------------
__device__ __align__(16) float g_B1[128 * 128];     // [W_e1 | W_s1], tf32-rounded
__device__ __align__(16) float g_B2[128 * 128];     // [W_e2 | W_s2], tf32-rounded
__device__ __align__(16) float g_z[2 * NN * 128];   // layer1: cols 0:64 = xn, 64:128 = xs
__device__ __align__(16) float g_y[2 * NN * 128];   // layer2: cols 0:64 = yn, 64:128 = ys
__device__ __align__(16) float g_h[2 * NN * 128];   // sigmoid(cat(xs, aggr))
__device__ __align__(16) float g_aggr[2 * NN * 64]; // layer1 aggregates
__device__ float g_si[2 * NN];
__device__ float g_sj[2 * NN];
__device__ float g_nsq[2 * NN];                     // ||aggr||^2
__device__ float g_norm[2 * NN * KNBR];             // final edge weights

__device__ __forceinline__ float sigmoidf_(float x) { return 1.f / (1.f + __expf(-x)); }
__device__ __forceinline__ float tf32r(float x) {
    float r; asm("cvt.rna.tf32.f32 %0, %1;" : "=f"(r) : "f"(x)); return r;
}

// ---------------- pack [We|Ws] into 128x128 B matrices (tf32-rounded) ----------------
__global__ void pack_B_kernel(const float* __restrict__ We1, const float* __restrict__ Ws1,
                              const float* __restrict__ We2, const float* __restrict__ Ws2) {
    int idx = blockIdx.x * blockDim.x + threadIdx.x;
    if (idx >= 128 * 128) return;
    int k = idx >> 7, j = idx & 127;
    g_B1[idx] = tf32r((j < 64) ? We1[k * 64 + j] : Ws1[k * 64 + (j - 64)]);
    g_B2[idx] = tf32r((j < 64) ? We2[k * 64 + j] : Ws2[k * 64 + (j - 64)]);
}

// ---------------- TF32 tensor-core GEMM: C[M,128] = A[M,128] @ B[128,128] ----------------
#define AS_STRIDE 132
#define BS_STRIDE 136
#define GEMM_SMEM ((128 * AS_STRIDE + 128 * BS_STRIDE) * 4)

__device__ __forceinline__ void mma_tf32(float* d, const uint32_t* a, uint32_t b0, uint32_t b1) {
    asm volatile(
        "mma.sync.aligned.m16n8k8.row.col.f32.tf32.tf32.f32 "
        "{%0,%1,%2,%3}, {%4,%5,%6,%7}, {%8,%9}, {%0,%1,%2,%3};"
        : "+f"(d[0]), "+f"(d[1]), "+f"(d[2]), "+f"(d[3])
        : "r"(a[0]), "r"(a[1]), "r"(a[2]), "r"(a[3]), "r"(b0), "r"(b1));
}

__global__ void gemm_tc(const float* __restrict__ x1, const float* __restrict__ x2, int layer) {
    extern __shared__ float sm[];
    float* As = sm;
    float* Bs = sm + 128 * AS_STRIDE;

    const int Mtot = 2 * NN;
    const float* __restrict__ Bg = (layer == 1) ? g_B1 : g_B2;
    float* __restrict__ C = (layer == 1) ? g_z : g_y;

    int tid = threadIdx.x;
    int rowBase = blockIdx.x * 128;

#pragma unroll
    for (int it = 0; it < 16; it++) {
        int row = (tid >> 5) + it * 8;
        int k4 = (tid & 31) * 4;
        int grow = rowBase + row;
        float4 v = {0.f, 0.f, 0.f, 0.f};
        if (grow < Mtot) {
            const float* src;
            if (layer == 1)
                src = (grow < NN) ? (x1 + (size_t)grow * 128) : (x2 + (size_t)(grow - NN) * 128);
            else
                src = g_h + (size_t)grow * 128;
            v = *(const float4*)(src + k4);
        }
        float4 c = {tf32r(v.x), tf32r(v.y), tf32r(v.z), tf32r(v.w)};
        *(float4*)&As[row * AS_STRIDE + k4] = c;
    }
#pragma unroll
    for (int it = 0; it < 16; it++) {
        int k = (tid >> 5) + it * 8;
        int n4 = (tid & 31) * 4;
        float4 v = *(const float4*)(Bg + k * 128 + n4);
        *(float4*)&Bs[k * BS_STRIDE + n4] = v;
    }
    __syncthreads();

    int lane = tid & 31;
    int wm = (tid >> 5) & 3;
    int wn = tid >> 7;
    int rA = wm * 32 + (lane >> 2);
    int kq = lane & 3;
    int nB = wn * 64 + (lane >> 2);

    float acc[2][8][4];
#pragma unroll
    for (int mf = 0; mf < 2; mf++)
#pragma unroll
        for (int nf = 0; nf < 8; nf++)
#pragma unroll
            for (int c = 0; c < 4; c++) acc[mf][nf][c] = 0.f;

#pragma unroll
    for (int ks = 0; ks < 16; ks++) {
        int kb = ks * 8;
        uint32_t a[2][4];
#pragma unroll
        for (int mf = 0; mf < 2; mf++) {
            int r = rA + mf * 16;
            a[mf][0] = __float_as_uint(As[r * AS_STRIDE + kb + kq]);
            a[mf][1] = __float_as_uint(As[(r + 8) * AS_STRIDE + kb + kq]);
            a[mf][2] = __float_as_uint(As[r * AS_STRIDE + kb + kq + 4]);
            a[mf][3] = __float_as_uint(As[(r + 8) * AS_STRIDE + kb + kq + 4]);
        }
#pragma unroll
        for (int nf = 0; nf < 8; nf++) {
            uint32_t b0 = __float_as_uint(Bs[(kb + kq) * BS_STRIDE + nB + nf * 8]);
            uint32_t b1 = __float_as_uint(Bs[(kb + kq + 4) * BS_STRIDE + nB + nf * 8]);
            mma_tf32(acc[0][nf], a[0], b0, b1);
            mma_tf32(acc[1][nf], a[1], b0, b1);
        }
    }

#pragma unroll
    for (int mf = 0; mf < 2; mf++) {
#pragma unroll
        for (int nf = 0; nf < 8; nf++) {
            int row = rowBase + wm * 32 + mf * 16 + (lane >> 2);
            int col = wn * 64 + nf * 8 + (lane & 3) * 2;
            if (row < Mtot) {
                float2 v0 = {acc[mf][nf][0], acc[mf][nf][1]};
                *(float2*)&C[(size_t)row * 128 + col] = v0;
            }
            if (row + 8 < Mtot) {
                float2 v1 = {acc[mf][nf][2], acc[mf][nf][3]};
                *(float2*)&C[(size_t)(row + 8) * 128 + col] = v1;
            }
        }
    }
}

// ---------------- layer-1 aggregate + h + attention scalars ----------------
__global__ void aggr_kernel(const int* __restrict__ nbr1, const int* __restrict__ nbr2,
                            const float* __restrict__ watt) {
    int t = threadIdx.x;
    int nodeLocal = t >> 4;
    int q = t & 15;
    int node = blockIdx.x * 16 + nodeLocal;
    int g = node >= NN;
    int i = g ? node - NN : node;
    const int* nbr = g ? nbr2 : nbr1;
    size_t gbase = (size_t)g * NN;

    int nid = __ldg(&nbr[i * 16 + q]);

    float4 s = {0.f, 0.f, 0.f, 0.f};
#pragma unroll
    for (int k = 0; k < 16; k++) {
        int j = __shfl_sync(0xffffffffu, nid, k, 16);
        float4 v = *(const float4*)&g_z[(gbase + j) * 128 + q * 4];
        s.x += v.x; s.y += v.y; s.z += v.z; s.w += v.w;
    }
    s.x *= (1.f / 16.f); s.y *= (1.f / 16.f); s.z *= (1.f / 16.f); s.w *= (1.f / 16.f);

    *(float4*)&g_aggr[(size_t)node * 64 + q * 4] = s;

    float4 xs = *(const float4*)&g_z[(size_t)node * 128 + 64 + q * 4];
    float4 hx = {sigmoidf_(xs.x), sigmoidf_(xs.y), sigmoidf_(xs.z), sigmoidf_(xs.w)};
    float4 ha = {sigmoidf_(s.x), sigmoidf_(s.y), sigmoidf_(s.z), sigmoidf_(s.w)};
    *(float4*)&g_h[(size_t)node * 128 + q * 4] = hx;
    *(float4*)&g_h[(size_t)node * 128 + 64 + q * 4] = ha;

    float4 w0 = *(const float4*)&watt[q * 4];
    float4 w1 = *(const float4*)&watt[64 + q * 4];
    float p0 = s.x * w0.x + s.y * w0.y + s.z * w0.z + s.w * w0.w;
    float p1 = s.x * w1.x + s.y * w1.y + s.z * w1.z + s.w * w1.w;
    float p2 = s.x * s.x + s.y * s.y + s.z * s.z + s.w * s.w;
#pragma unroll
    for (int o = 8; o; o >>= 1) {
        p0 += __shfl_xor_sync(0xffffffffu, p0, o);
        p1 += __shfl_xor_sync(0xffffffffu, p1, o);
        p2 += __shfl_xor_sync(0xffffffffu, p2, o);
    }
    if (q == 0) {
        g_si[node] = p0;
        g_sj[node] = p1;
        g_nsq[node] = p2;
    }
}

// ---------------- cross-attn + self-attn -> final edge weights ----------------
// One warp per node; 4 warps / block. Swizzled smem tiles (conflict-free),
// float4 gather, all sim reductions in registers via shuffles.
// Swizzle: float4 index = row*16 + (d4 ^ (row>>1)).
__global__ void attn_kernel(const int* __restrict__ nbr1, const int* __restrict__ nbr2) {
    __shared__ float4 sm[4][512];          // per warp: a1 [16][16] f4 | a2 [16][16] f4
    int warp = threadIdx.x >> 5;
    int lane = threadIdx.x & 31;
    int i = blockIdx.x * 4 + warp;
    float4* a1s = sm[warp];
    float4* a2s = sm[warp] + 256;

    int nid;
    if (lane < 16) nid = nbr1[i * 16 + lane];
    else           nid = nbr2[i * 16 + (lane - 16)];

    // ---- gather 32 rows x 64 floats as float4, swizzled ----
#pragma unroll
    for (int it = 0; it < 16; it++) {
        int idx = it * 32 + lane;          // 0..511
        int arr = idx >> 8;                // 0 = a1, 1 = a2
        int local = idx & 255;
        int row = local >> 4, d4 = local & 15;
        int j = __shfl_sync(0xffffffffu, nid, arr * 16 + row);
        const float4* src = (const float4*)g_aggr + ((size_t)(arr ? NN : 0) + j) * 16 + d4;
        sm[warp][arr * 256 + row * 16 + (d4 ^ (row >> 1))] = *src;
    }
    float myNsq = (lane < 16) ? g_nsq[nid] : g_nsq[NN + nid];
    __syncwarp();

    // ---- 16x16 Gram: lane = (kg = lane>>2 -> rows 2kg,2kg+1) x (lg = lane&3 -> cols 4lg..4lg+3)
    int kg = lane >> 2;
    int lg = lane & 3;
    int r0 = kg * 2, r1 = kg * 2 + 1;
    float acc0[4] = {0, 0, 0, 0};
    float acc1[4] = {0, 0, 0, 0};
#pragma unroll
    for (int d4 = 0; d4 < 16; d4++) {
        float4 a0 = a1s[r0 * 16 + (d4 ^ (r0 >> 1))];
        float4 a1 = a1s[r1 * 16 + (d4 ^ (r1 >> 1))];
#pragma unroll
        for (int t = 0; t < 4; t++) {
            int r = lg * 4 + t;
            float4 b = a2s[r * 16 + (d4 ^ (r >> 1))];
            acc0[t] += a0.x * b.x + a0.y * b.y + a0.z * b.z + a0.w * b.w;
            acc1[t] += a1.x * b.x + a1.y * b.y + a1.z * b.z + a1.w * b.w;
        }
    }

    float nsqK0 = __shfl_sync(0xffffffffu, myNsq, r0);
    float nsqK1 = __shfl_sync(0xffffffffu, myNsq, r1);
    float sim0[4], sim1[4];
#pragma unroll
    for (int t = 0; t < 4; t++) {
        float nsqL = __shfl_sync(0xffffffffu, myNsq, 16 + lg * 4 + t);
        float d20 = nsqK0 + nsqL - 2.f * acc0[t];
        float d21 = nsqK1 + nsqL - 2.f * acc1[t];
        sim0[t] = __expf(-sqrtf(fmaxf(d20, 1e-12f)));
        sim1[t] = __expf(-sqrtf(fmaxf(d21, 1e-12f)));
    }

    // ---- reductions in registers ----
    float s0 = sim0[0] + sim0[1] + sim0[2] + sim0[3];   // partial row sum, row r0
    float s1 = sim1[0] + sim1[1] + sim1[2] + sim1[3];   // partial row sum, row r1
    float c0 = sim0[0] + sim1[0], c1 = sim0[1] + sim1[1];
    float c2 = sim0[2] + sim1[2], c3 = sim0[3] + sim1[3];
    float tot = s0 + s1;

    // row sums: reduce over lg (lanes differing in bits 0,1)
    s0 += __shfl_xor_sync(0xffffffffu, s0, 1); s1 += __shfl_xor_sync(0xffffffffu, s1, 1);
    s0 += __shfl_xor_sync(0xffffffffu, s0, 2); s1 += __shfl_xor_sync(0xffffffffu, s1, 2);
    // col sums: reduce over kg (bits 2,3,4)
#pragma unroll
    for (int o = 4; o <= 16; o <<= 1) {
        c0 += __shfl_xor_sync(0xffffffffu, c0, o);
        c1 += __shfl_xor_sync(0xffffffffu, c1, o);
        c2 += __shfl_xor_sync(0xffffffffu, c2, o);
        c3 += __shfl_xor_sync(0xffffffffu, c3, o);
    }
    // grand total: full warp reduction
#pragma unroll
    for (int o = 16; o; o >>= 1) tot += __shfl_xor_sync(0xffffffffu, tot, o);

    // route row sum k to lane k (lanes 0-15), col sum l to lane 16+l
    int kl = lane & 15;
    int srcR = (kl >> 1) << 2;                 // a lane holding rows kl&~1, kl|1
    float rs0 = __shfl_sync(0xffffffffu, s0, srcR);
    float rs1 = __shfl_sync(0xffffffffu, s1, srcR);
    float rowval = (kl & 1) ? rs1 : rs0;
    int srcC = kl >> 2;                        // lane with lg == l>>2
    float ct0 = __shfl_sync(0xffffffffu, c0, srcC);
    float ct1 = __shfl_sync(0xffffffffu, c1, srcC);
    float ct2 = __shfl_sync(0xffffffffu, c2, srcC);
    float ct3 = __shfl_sync(0xffffffffu, c3, srcC);
    int tt = kl & 3;
    float colval = (tt == 0) ? ct0 : (tt == 1) ? ct1 : (tt == 2) ? ct2 : ct3;

    float cross = ((lane < 16) ? rowval : colval) / tot;

    // self-attention softmax per graph half (lanes 0-15 = g1, 16-31 = g2)
    float sii = (lane < 16) ? g_si[i] : g_si[NN + i];
    float sjv = (lane < 16) ? g_sj[nid] : g_sj[NN + nid];
    float zz = sii + sjv;
    float lr = (zz >= 0.f) ? zz : 0.01f * zz;
    float e = __expf(lr);
    float esum = e;
#pragma unroll
    for (int o = 8; o; o >>= 1) esum += __shfl_xor_sync(0xffffffffu, esum, o);

    float nrm = cross * (e / esum);
    if (lane < 16) g_norm[(size_t)i * 16 + lane] = nrm;
    else           g_norm[(size_t)(NN + i) * 16 + (lane - 16)] = nrm;
}

// ---------------- final weighted aggregate + sigmoid -> output ----------------
__global__ void out_kernel(const int* __restrict__ nbr1, const int* __restrict__ nbr2,
                           float* __restrict__ out) {
    int t = threadIdx.x;
    int nodeLocal = t >> 4;
    int q = t & 15;
    int node = blockIdx.x * 16 + nodeLocal;
    int g = node >= NN;
    int i = g ? node - NN : node;
    const int* nbr = g ? nbr2 : nbr1;
    size_t gbase = (size_t)g * NN;

    int nid = __ldg(&nbr[i * 16 + q]);
    float wq = g_norm[(size_t)node * 16 + q];

    float4 s = {0.f, 0.f, 0.f, 0.f};
#pragma unroll
    for (int k = 0; k < 16; k++) {
        int j = __shfl_sync(0xffffffffu, nid, k, 16);
        float w = __shfl_sync(0xffffffffu, wq, k, 16);
        float4 v = *(const float4*)&g_y[(gbase + j) * 128 + q * 4];
        s.x += w * v.x; s.y += w * v.y; s.z += w * v.z; s.w += w * v.w;
    }

    float4 ys = *(const float4*)&g_y[(size_t)node * 128 + 64 + q * 4];
    float4 o0 = {sigmoidf_(ys.x), sigmoidf_(ys.y), sigmoidf_(ys.z), sigmoidf_(ys.w)};
    float4 o1 = {sigmoidf_(s.x), sigmoidf_(s.y), sigmoidf_(s.z), sigmoidf_(s.w)};
    *(float4*)&out[(size_t)node * 128 + q * 4] = o0;
    *(float4*)&out[(size_t)node * 128 + 64 + q * 4] = o1;
}

// ---------------- launch ----------------
extern "C" void kernel_launch(void* const* d_in, const int* in_sizes, int n_in,
                              void* d_out, int out_size) {
    const float* x1   = (const float*)d_in[0];
    const float* x2   = (const float*)d_in[1];
    const int*   nbr1 = (const int*)d_in[2];
    const int*   nbr2 = (const int*)d_in[3];
    const float* We1  = (const float*)d_in[4];
    const float* Ws1  = (const float*)d_in[5];
    const float* We2  = (const float*)d_in[6];
    const float* Ws2  = (const float*)d_in[7];
    const float* watt = (const float*)d_in[8];
    float* out = (float*)d_out;

    cudaFuncSetAttribute(gemm_tc, cudaFuncAttributeMaxDynamicSharedMemorySize, GEMM_SMEM);

    pack_B_kernel<<<64, 256>>>(We1, Ws1, We2, Ws2);

    int gb = (2 * NN + 127) / 128;
    gemm_tc<<<gb, 256, GEMM_SMEM>>>(x1, x2, 1);

    aggr_kernel<<<(2 * NN) / 16, 256>>>(nbr1, nbr2, watt);
    attn_kernel<<<NN / 4, 128>>>(nbr1, nbr2);

    gemm_tc<<<gb, 256, GEMM_SMEM>>>(x1, x2, 2);

    out_kernel<<<(2 * NN) / 16, 256>>>(nbr1, nbr2, out);
}

// round 4
// speedup vs baseline: 2.9465x; 1.3791x over previous
#include <cuda_runtime.h>
#include <cstdint>

#define NN 50000
#define KNBR 16

// ---------------- scratch (device globals; no runtime allocation) ----------------
__device__ __align__(16) float g_B1[128 * 128];     // [W_e1 | W_s1], tf32-rounded
__device__ __align__(16) float g_B2[128 * 128];     // [W_e2 | W_s2], tf32-rounded
__device__ __align__(16) float g_z[2 * NN * 128];   // layer1: cols 0:64 = xn, 64:128 = xs
__device__ __align__(16) float g_y[2 * NN * 128];   // layer2: cols 0:64 = yn, 64:128 = ys
__device__ __align__(16) float g_h[2 * NN * 128];   // sigmoid(cat(xs, aggr))
__device__ __align__(16) float g_aggr[2 * NN * 64]; // layer1 aggregates
__device__ float g_si[2 * NN];
__device__ float g_sj[2 * NN];
__device__ float g_nsq[2 * NN];                     // ||aggr||^2 (exact fp32)
__device__ float g_norm[2 * NN * KNBR];             // final edge weights

__device__ __forceinline__ float sigmoidf_(float x) { return 1.f / (1.f + __expf(-x)); }
__device__ __forceinline__ float tf32r(float x) {
    float r; asm("cvt.rna.tf32.f32 %0, %1;" : "=f"(r) : "f"(x)); return r;
}

__device__ __forceinline__ void mma_tf32(float* d, const uint32_t* a, uint32_t b0, uint32_t b1) {
    asm volatile(
        "mma.sync.aligned.m16n8k8.row.col.f32.tf32.tf32.f32 "
        "{%0,%1,%2,%3}, {%4,%5,%6,%7}, {%8,%9}, {%0,%1,%2,%3};"
        : "+f"(d[0]), "+f"(d[1]), "+f"(d[2]), "+f"(d[3])
        : "r"(a[0]), "r"(a[1]), "r"(a[2]), "r"(a[3]), "r"(b0), "r"(b1));
}

// ---------------- pack [We|Ws] into 128x128 B matrices (tf32-rounded) ----------------
__global__ void pack_B_kernel(const float* __restrict__ We1, const float* __restrict__ Ws1,
                              const float* __restrict__ We2, const float* __restrict__ Ws2) {
    int idx = blockIdx.x * blockDim.x + threadIdx.x;
    if (idx >= 128 * 128) return;
    int k = idx >> 7, j = idx & 127;
    g_B1[idx] = tf32r((j < 64) ? We1[k * 64 + j] : Ws1[k * 64 + (j - 64)]);
    g_B2[idx] = tf32r((j < 64) ? We2[k * 64 + j] : Ws2[k * 64 + (j - 64)]);
}

// ---------------- TF32 tensor-core GEMM: C[M,128] = A[M,128] @ B[128,128] ----------------
// BK=64, two stages; smem 69.6KB -> 2 blocks/SM.
#define AS_STRIDE 68
#define BS_STRIDE 136
#define GEMM_SMEM ((128 * AS_STRIDE + 64 * BS_STRIDE) * 4)

__global__ void gemm_tc(const float* __restrict__ x1, const float* __restrict__ x2, int layer) {
    extern __shared__ float sm[];
    float* As = sm;                      // [128][AS_STRIDE], one K-half
    float* Bs = sm + 128 * AS_STRIDE;    // [64][BS_STRIDE]

    const int Mtot = 2 * NN;
    const float* __restrict__ Bg = (layer == 1) ? g_B1 : g_B2;
    float* __restrict__ C = (layer == 1) ? g_z : g_y;

    int tid = threadIdx.x;
    int rowBase = blockIdx.x * 128;

    int lane = tid & 31;
    int wm = (tid >> 5) & 3;
    int wn = tid >> 7;
    int rA = wm * 32 + (lane >> 2);
    int kq = lane & 3;
    int nB = wn * 64 + (lane >> 2);

    float acc[2][8][4];
#pragma unroll
    for (int mf = 0; mf < 2; mf++)
#pragma unroll
        for (int nf = 0; nf < 8; nf++)
#pragma unroll
            for (int c = 0; c < 4; c++) acc[mf][nf][c] = 0.f;

    for (int kh = 0; kh < 2; kh++) {
        // ---- load A half tile (tf32-round) : 128 rows x 64 cols ----
#pragma unroll
        for (int it = 0; it < 8; it++) {
            int row = (tid >> 4) + it * 16;
            int c4 = (tid & 15) * 4;
            int grow = rowBase + row;
            float4 v = {0.f, 0.f, 0.f, 0.f};
            if (grow < Mtot) {
                const float* src;
                if (layer == 1)
                    src = (grow < NN) ? (x1 + (size_t)grow * 128) : (x2 + (size_t)(grow - NN) * 128);
                else
                    src = g_h + (size_t)grow * 128;
                v = *(const float4*)(src + kh * 64 + c4);
            }
            float4 c = {tf32r(v.x), tf32r(v.y), tf32r(v.z), tf32r(v.w)};
            *(float4*)&As[row * AS_STRIDE + c4] = c;
        }
        // ---- load B half tile : 64 k-rows x 128 cols ----
#pragma unroll
        for (int it = 0; it < 8; it++) {
            int k = (tid >> 5) + it * 8;
            int n4 = (tid & 31) * 4;
            float4 v = *(const float4*)(Bg + (size_t)(kh * 64 + k) * 128 + n4);
            *(float4*)&Bs[k * BS_STRIDE + n4] = v;
        }
        __syncthreads();

#pragma unroll
        for (int ks = 0; ks < 8; ks++) {
            int kb = ks * 8;
            uint32_t a[2][4];
#pragma unroll
            for (int mf = 0; mf < 2; mf++) {
                int r = rA + mf * 16;
                a[mf][0] = __float_as_uint(As[r * AS_STRIDE + kb + kq]);
                a[mf][1] = __float_as_uint(As[(r + 8) * AS_STRIDE + kb + kq]);
                a[mf][2] = __float_as_uint(As[r * AS_STRIDE + kb + kq + 4]);
                a[mf][3] = __float_as_uint(As[(r + 8) * AS_STRIDE + kb + kq + 4]);
            }
#pragma unroll
            for (int nf = 0; nf < 8; nf++) {
                uint32_t b0 = __float_as_uint(Bs[(kb + kq) * BS_STRIDE + nB + nf * 8]);
                uint32_t b1 = __float_as_uint(Bs[(kb + kq + 4) * BS_STRIDE + nB + nf * 8]);
                mma_tf32(acc[0][nf], a[0], b0, b1);
                mma_tf32(acc[1][nf], a[1], b0, b1);
            }
        }
        __syncthreads();
    }

#pragma unroll
    for (int mf = 0; mf < 2; mf++) {
#pragma unroll
        for (int nf = 0; nf < 8; nf++) {
            int row = rowBase + wm * 32 + mf * 16 + (lane >> 2);
            int col = wn * 64 + nf * 8 + (lane & 3) * 2;
            if (row < Mtot) {
                float2 v0 = {acc[mf][nf][0], acc[mf][nf][1]};
                *(float2*)&C[(size_t)row * 128 + col] = v0;
            }
            if (row + 8 < Mtot) {
                float2 v1 = {acc[mf][nf][2], acc[mf][nf][3]};
                *(float2*)&C[(size_t)(row + 8) * 128 + col] = v1;
            }
        }
    }
}

// ---------------- layer-1 aggregate + h + attention scalars ----------------
__global__ void aggr_kernel(const int* __restrict__ nbr1, const int* __restrict__ nbr2,
                            const float* __restrict__ watt) {
    int t = threadIdx.x;
    int nodeLocal = t >> 4;
    int q = t & 15;
    int node = blockIdx.x * 16 + nodeLocal;
    int g = node >= NN;
    int i = g ? node - NN : node;
    const int* nbr = g ? nbr2 : nbr1;
    size_t gbase = (size_t)g * NN;

    int nid = __ldg(&nbr[i * 16 + q]);

    float4 s = {0.f, 0.f, 0.f, 0.f};
#pragma unroll
    for (int k = 0; k < 16; k++) {
        int j = __shfl_sync(0xffffffffu, nid, k, 16);
        float4 v = *(const float4*)&g_z[(gbase + j) * 128 + q * 4];
        s.x += v.x; s.y += v.y; s.z += v.z; s.w += v.w;
    }
    s.x *= (1.f / 16.f); s.y *= (1.f / 16.f); s.z *= (1.f / 16.f); s.w *= (1.f / 16.f);

    *(float4*)&g_aggr[(size_t)node * 64 + q * 4] = s;

    float4 xs = *(const float4*)&g_z[(size_t)node * 128 + 64 + q * 4];
    float4 hx = {sigmoidf_(xs.x), sigmoidf_(xs.y), sigmoidf_(xs.z), sigmoidf_(xs.w)};
    float4 ha = {sigmoidf_(s.x), sigmoidf_(s.y), sigmoidf_(s.z), sigmoidf_(s.w)};
    *(float4*)&g_h[(size_t)node * 128 + q * 4] = hx;
    *(float4*)&g_h[(size_t)node * 128 + 64 + q * 4] = ha;

    float4 w0 = *(const float4*)&watt[q * 4];
    float4 w1 = *(const float4*)&watt[64 + q * 4];
    float p0 = s.x * w0.x + s.y * w0.y + s.z * w0.z + s.w * w0.w;
    float p1 = s.x * w1.x + s.y * w1.y + s.z * w1.z + s.w * w1.w;
    float p2 = s.x * s.x + s.y * s.y + s.z * s.z + s.w * s.w;
#pragma unroll
    for (int o = 8; o; o >>= 1) {
        p0 += __shfl_xor_sync(0xffffffffu, p0, o);
        p1 += __shfl_xor_sync(0xffffffffu, p1, o);
        p2 += __shfl_xor_sync(0xffffffffu, p2, o);
    }
    if (q == 0) {
        g_si[node] = p0;
        g_sj[node] = p1;
        g_nsq[node] = p2;
    }
}

// ---------------- cross-attn + self-attn via tensor-core Gram ----------------
// One warp per node; 4 warps / block. Gram S = A1 @ A2^T via 16x mma.m16n8k8.tf32.
// Tiles stride 68 floats: fragment loads hit banks 4*row + kq -> conflict-free.
#define AT_STRIDE 68
__global__ void attn_kernel(const int* __restrict__ nbr1, const int* __restrict__ nbr2) {
    __shared__ float sm[4][2 * 16 * AT_STRIDE];   // per warp: a1[16][68] | a2[16][68]
    int warp = threadIdx.x >> 5;
    int lane = threadIdx.x & 31;
    int i = blockIdx.x * 4 + warp;
    float* a1s = sm[warp];
    float* a2s = sm[warp] + 16 * AT_STRIDE;

    int nid;
    if (lane < 16) nid = nbr1[i * 16 + lane];
    else           nid = nbr2[i * 16 + (lane - 16)];

    // ---- gather 32 rows x 64 floats (coalesced float4) ----
#pragma unroll
    for (int it = 0; it < 16; it++) {
        int idx = it * 32 + lane;          // 0..511
        int arr = idx >> 8;                // 0 = a1, 1 = a2
        int local = idx & 255;
        int row = local >> 4, d4 = local & 15;
        int j = __shfl_sync(0xffffffffu, nid, arr * 16 + row);
        float4 v = *((const float4*)g_aggr + ((size_t)(arr ? NN : 0) + j) * 16 + d4);
        *(float4*)&sm[warp][arr * 16 * AT_STRIDE + row * AT_STRIDE + d4 * 4] = v;
    }
    float myNsq = (lane < 16) ? g_nsq[nid] : g_nsq[NN + nid];
    __syncwarp();

    // ---- Gram via mma: rows 16, cols 16 (2 n-tiles of 8), K = 64 (8 k-steps) ----
    int rq = lane >> 2;                   // 0..7
    int kq = lane & 3;                    // 0..3
    float acc[2][4];
#pragma unroll
    for (int nt = 0; nt < 2; nt++)
#pragma unroll
        for (int c = 0; c < 4; c++) acc[nt][c] = 0.f;

#pragma unroll
    for (int ks = 0; ks < 8; ks++) {
        int kb = ks * 8;
        uint32_t a[4];
        a[0] = __float_as_uint(a1s[rq * AT_STRIDE + kb + kq]);
        a[1] = __float_as_uint(a1s[(rq + 8) * AT_STRIDE + kb + kq]);
        a[2] = __float_as_uint(a1s[rq * AT_STRIDE + kb + kq + 4]);
        a[3] = __float_as_uint(a1s[(rq + 8) * AT_STRIDE + kb + kq + 4]);
#pragma unroll
        for (int nt = 0; nt < 2; nt++) {
            // B col-major fragment: B[k][n] = A2[n][k]
            uint32_t b0 = __float_as_uint(a2s[(nt * 8 + rq) * AT_STRIDE + kb + kq]);
            uint32_t b1 = __float_as_uint(a2s[(nt * 8 + rq) * AT_STRIDE + kb + kq + 4]);
            mma_tf32(acc[nt], a, b0, b1);
        }
    }

    // ---- sims + marginals; C frag: rows {rq, rq+8}, cols nt*8 + 2kq + {0,1} ----
    float nsqK0 = __shfl_sync(0xffffffffu, myNsq, rq);
    float nsqK1 = __shfl_sync(0xffffffffu, myNsq, rq + 8);
    float rp0 = 0.f, rp1 = 0.f;           // row partials for rows rq, rq+8
    float cp[2][2];                        // col partials [nt][parity]
#pragma unroll
    for (int nt = 0; nt < 2; nt++) {
        float nsqL0 = __shfl_sync(0xffffffffu, myNsq, 16 + nt * 8 + 2 * kq);
        float nsqL1 = __shfl_sync(0xffffffffu, myNsq, 16 + nt * 8 + 2 * kq + 1);
        float s00 = __expf(-sqrtf(fmaxf(nsqK0 + nsqL0 - 2.f * acc[nt][0], 1e-12f)));
        float s01 = __expf(-sqrtf(fmaxf(nsqK0 + nsqL1 - 2.f * acc[nt][1], 1e-12f)));
        float s10 = __expf(-sqrtf(fmaxf(nsqK1 + nsqL0 - 2.f * acc[nt][2], 1e-12f)));
        float s11 = __expf(-sqrtf(fmaxf(nsqK1 + nsqL1 - 2.f * acc[nt][3], 1e-12f)));
        rp0 += s00 + s01;
        rp1 += s10 + s11;
        cp[nt][0] = s00 + s10;
        cp[nt][1] = s01 + s11;
    }
    float tot = rp0 + rp1;
#pragma unroll
    for (int o = 16; o; o >>= 1) tot += __shfl_xor_sync(0xffffffffu, tot, o);

    // row sums: reduce over kq (lane bits 0,1)
    rp0 += __shfl_xor_sync(0xffffffffu, rp0, 1);
    rp1 += __shfl_xor_sync(0xffffffffu, rp1, 1);
    rp0 += __shfl_xor_sync(0xffffffffu, rp0, 2);
    rp1 += __shfl_xor_sync(0xffffffffu, rp1, 2);
    // col sums: reduce over rq (lane bits 2,3,4)
#pragma unroll
    for (int o = 4; o <= 16; o <<= 1) {
        cp[0][0] += __shfl_xor_sync(0xffffffffu, cp[0][0], o);
        cp[0][1] += __shfl_xor_sync(0xffffffffu, cp[0][1], o);
        cp[1][0] += __shfl_xor_sync(0xffffffffu, cp[1][0], o);
        cp[1][1] += __shfl_xor_sync(0xffffffffu, cp[1][1], o);
    }

    // route: lane k (0-15) needs rowsum(k); lane 16+l needs colsum(l)
    int kl = lane & 15;
    float r0v = __shfl_sync(0xffffffffu, rp0, 4 * (kl & 7));
    float r1v = __shfl_sync(0xffffffffu, rp1, 4 * (kl & 7));
    float rowval = (kl < 8) ? r0v : r1v;
    int srcC = (kl & 7) >> 1;              // lane with kq == (l&7)>>1
    float c00 = __shfl_sync(0xffffffffu, cp[0][0], srcC);
    float c01 = __shfl_sync(0xffffffffu, cp[0][1], srcC);
    float c10 = __shfl_sync(0xffffffffu, cp[1][0], srcC);
    float c11 = __shfl_sync(0xffffffffu, cp[1][1], srcC);
    float colval = (kl >> 3) ? ((kl & 1) ? c11 : c10) : ((kl & 1) ? c01 : c00);

    float cross = ((lane < 16) ? rowval : colval) / tot;

    // self-attention softmax per graph half
    float sii = (lane < 16) ? g_si[i] : g_si[NN + i];
    float sjv = (lane < 16) ? g_sj[nid] : g_sj[NN + nid];
    float zz = sii + sjv;
    float lr = (zz >= 0.f) ? zz : 0.01f * zz;
    float e = __expf(lr);
    float esum = e;
#pragma unroll
    for (int o = 8; o; o >>= 1) esum += __shfl_xor_sync(0xffffffffu, esum, o);

    float nrm = cross * (e / esum);
    if (lane < 16) g_norm[(size_t)i * 16 + lane] = nrm;
    else           g_norm[(size_t)(NN + i) * 16 + (lane - 16)] = nrm;
}

// ---------------- final weighted aggregate + sigmoid -> output ----------------
__global__ void out_kernel(const int* __restrict__ nbr1, const int* __restrict__ nbr2,
                           float* __restrict__ out) {
    int t = threadIdx.x;
    int nodeLocal = t >> 4;
    int q = t & 15;
    int node = blockIdx.x * 16 + nodeLocal;
    int g = node >= NN;
    int i = g ? node - NN : node;
    const int* nbr = g ? nbr2 : nbr1;
    size_t gbase = (size_t)g * NN;

    int nid = __ldg(&nbr[i * 16 + q]);
    float wq = g_norm[(size_t)node * 16 + q];

    float4 s = {0.f, 0.f, 0.f, 0.f};
#pragma unroll
    for (int k = 0; k < 16; k++) {
        int j = __shfl_sync(0xffffffffu, nid, k, 16);
        float w = __shfl_sync(0xffffffffu, wq, k, 16);
        float4 v = *(const float4*)&g_y[(gbase + j) * 128 + q * 4];
        s.x += w * v.x; s.y += w * v.y; s.z += w * v.z; s.w += w * v.w;
    }

    float4 ys = *(const float4*)&g_y[(size_t)node * 128 + 64 + q * 4];
    float4 o0 = {sigmoidf_(ys.x), sigmoidf_(ys.y), sigmoidf_(ys.z), sigmoidf_(ys.w)};
    float4 o1 = {sigmoidf_(s.x), sigmoidf_(s.y), sigmoidf_(s.z), sigmoidf_(s.w)};
    *(float4*)&out[(size_t)node * 128 + q * 4] = o0;
    *(float4*)&out[(size_t)node * 128 + 64 + q * 4] = o1;
}

// ---------------- launch ----------------
extern "C" void kernel_launch(void* const* d_in, const int* in_sizes, int n_in,
                              void* d_out, int out_size) {
    const float* x1   = (const float*)d_in[0];
    const float* x2   = (const float*)d_in[1];
    const int*   nbr1 = (const int*)d_in[2];
    const int*   nbr2 = (const int*)d_in[3];
    const float* We1  = (const float*)d_in[4];
    const float* Ws1  = (const float*)d_in[5];
    const float* We2  = (const float*)d_in[6];
    const float* Ws2  = (const float*)d_in[7];
    const float* watt = (const float*)d_in[8];
    float* out = (float*)d_out;

    cudaFuncSetAttribute(gemm_tc, cudaFuncAttributeMaxDynamicSharedMemorySize, GEMM_SMEM);

    pack_B_kernel<<<64, 256>>>(We1, Ws1, We2, Ws2);

    int gb = (2 * NN + 127) / 128;
    gemm_tc<<<gb, 256, GEMM_SMEM>>>(x1, x2, 1);

    aggr_kernel<<<(2 * NN) / 16, 256>>>(nbr1, nbr2, watt);
    attn_kernel<<<NN / 4, 128>>>(nbr1, nbr2);

    gemm_tc<<<gb, 256, GEMM_SMEM>>>(x1, x2, 2);

    out_kernel<<<(2 * NN) / 16, 256>>>(nbr1, nbr2, out);
}

// round 5
// speedup vs baseline: 3.3056x; 1.1219x over previous
#include <cuda_runtime.h>
#include <cuda_fp16.h>
#include <cstdint>

#define NN 50000
#define KNBR 16

// ---------------- scratch (device globals; no runtime allocation) ----------------
__device__ __align__(16) float g_B1[128 * 128];     // [W_e1 | W_s1], tf32-rounded
__device__ __align__(16) float g_B2[128 * 128];     // [W_e2 | W_s2], tf32-rounded
__device__ __align__(16) float g_z[2 * NN * 128];   // layer1 fp32 (xs cols used)
__device__ __align__(16) float g_y[2 * NN * 128];   // layer2 fp32 (ys cols used)
__device__ __align__(16) __half g_zn_h[2 * NN * 64];  // xn in fp16 (gather operand)
__device__ __align__(16) __half g_yn_h[2 * NN * 64];  // yn in fp16 (gather operand)
__device__ __align__(16) float g_h[2 * NN * 128];   // sigmoid(cat(xs, aggr))
__device__ __align__(16) __half g_aggr_h[2 * NN * 64]; // layer1 aggregates, fp16
__device__ float g_si[2 * NN];
__device__ float g_sj[2 * NN];
__device__ float g_nsq[2 * NN];                     // ||half(aggr)||^2 in fp32
__device__ float g_norm[2 * NN * KNBR];             // final edge weights

__device__ __forceinline__ float sigmoidf_(float x) { return 1.f / (1.f + __expf(-x)); }
__device__ __forceinline__ float tf32r(float x) {
    float r; asm("cvt.rna.tf32.f32 %0, %1;" : "=f"(r) : "f"(x)); return r;
}

__device__ __forceinline__ void mma_tf32(float* d, const uint32_t* a, uint32_t b0, uint32_t b1) {
    asm volatile(
        "mma.sync.aligned.m16n8k8.row.col.f32.tf32.tf32.f32 "
        "{%0,%1,%2,%3}, {%4,%5,%6,%7}, {%8,%9}, {%0,%1,%2,%3};"
        : "+f"(d[0]), "+f"(d[1]), "+f"(d[2]), "+f"(d[3])
        : "r"(a[0]), "r"(a[1]), "r"(a[2]), "r"(a[3]), "r"(b0), "r"(b1));
}

__device__ __forceinline__ void mma_f16(float* d, const uint32_t* a, uint32_t b0, uint32_t b1) {
    asm volatile(
        "mma.sync.aligned.m16n8k16.row.col.f32.f16.f16.f32 "
        "{%0,%1,%2,%3}, {%4,%5,%6,%7}, {%8,%9}, {%0,%1,%2,%3};"
        : "+f"(d[0]), "+f"(d[1]), "+f"(d[2]), "+f"(d[3])
        : "r"(a[0]), "r"(a[1]), "r"(a[2]), "r"(a[3]), "r"(b0), "r"(b1));
}

// ---------------- pack [We|Ws] into 128x128 B matrices (tf32-rounded) ----------------
__global__ void pack_B_kernel(const float* __restrict__ We1, const float* __restrict__ Ws1,
                              const float* __restrict__ We2, const float* __restrict__ Ws2) {
    int idx = blockIdx.x * blockDim.x + threadIdx.x;
    if (idx >= 128 * 128) return;
    int k = idx >> 7, j = idx & 127;
    g_B1[idx] = tf32r((j < 64) ? We1[k * 64 + j] : Ws1[k * 64 + (j - 64)]);
    g_B2[idx] = tf32r((j < 64) ? We2[k * 64 + j] : Ws2[k * 64 + (j - 64)]);
}

// ---------------- TF32 tensor-core GEMM: C[M,128] = A[M,128] @ B[128,128] ----------------
// BK=64, two stages; also emits fp16 copy of cols 0:64 (the gather operand).
#define AS_STRIDE 68
#define BS_STRIDE 136
#define GEMM_SMEM ((128 * AS_STRIDE + 64 * BS_STRIDE) * 4)

__global__ void gemm_tc(const float* __restrict__ x1, const float* __restrict__ x2, int layer) {
    extern __shared__ float sm[];
    float* As = sm;                      // [128][AS_STRIDE], one K-half
    float* Bs = sm + 128 * AS_STRIDE;    // [64][BS_STRIDE]

    const int Mtot = 2 * NN;
    const float* __restrict__ Bg = (layer == 1) ? g_B1 : g_B2;
    float* __restrict__ C = (layer == 1) ? g_z : g_y;
    __half* __restrict__ Ch = (layer == 1) ? g_zn_h : g_yn_h;

    int tid = threadIdx.x;
    int rowBase = blockIdx.x * 128;

    int lane = tid & 31;
    int wm = (tid >> 5) & 3;
    int wn = tid >> 7;
    int rA = wm * 32 + (lane >> 2);
    int kq = lane & 3;
    int nB = wn * 64 + (lane >> 2);

    float acc[2][8][4];
#pragma unroll
    for (int mf = 0; mf < 2; mf++)
#pragma unroll
        for (int nf = 0; nf < 8; nf++)
#pragma unroll
            for (int c = 0; c < 4; c++) acc[mf][nf][c] = 0.f;

    for (int kh = 0; kh < 2; kh++) {
#pragma unroll
        for (int it = 0; it < 8; it++) {
            int row = (tid >> 4) + it * 16;
            int c4 = (tid & 15) * 4;
            int grow = rowBase + row;
            float4 v = {0.f, 0.f, 0.f, 0.f};
            if (grow < Mtot) {
                const float* src;
                if (layer == 1)
                    src = (grow < NN) ? (x1 + (size_t)grow * 128) : (x2 + (size_t)(grow - NN) * 128);
                else
                    src = g_h + (size_t)grow * 128;
                v = *(const float4*)(src + kh * 64 + c4);
            }
            float4 c = {tf32r(v.x), tf32r(v.y), tf32r(v.z), tf32r(v.w)};
            *(float4*)&As[row * AS_STRIDE + c4] = c;
        }
#pragma unroll
        for (int it = 0; it < 8; it++) {
            int k = (tid >> 5) + it * 8;
            int n4 = (tid & 31) * 4;
            float4 v = *(const float4*)(Bg + (size_t)(kh * 64 + k) * 128 + n4);
            *(float4*)&Bs[k * BS_STRIDE + n4] = v;
        }
        __syncthreads();

#pragma unroll
        for (int ks = 0; ks < 8; ks++) {
            int kb = ks * 8;
            uint32_t a[2][4];
#pragma unroll
            for (int mf = 0; mf < 2; mf++) {
                int r = rA + mf * 16;
                a[mf][0] = __float_as_uint(As[r * AS_STRIDE + kb + kq]);
                a[mf][1] = __float_as_uint(As[(r + 8) * AS_STRIDE + kb + kq]);
                a[mf][2] = __float_as_uint(As[r * AS_STRIDE + kb + kq + 4]);
                a[mf][3] = __float_as_uint(As[(r + 8) * AS_STRIDE + kb + kq + 4]);
            }
#pragma unroll
            for (int nf = 0; nf < 8; nf++) {
                uint32_t b0 = __float_as_uint(Bs[(kb + kq) * BS_STRIDE + nB + nf * 8]);
                uint32_t b1 = __float_as_uint(Bs[(kb + kq + 4) * BS_STRIDE + nB + nf * 8]);
                mma_tf32(acc[0][nf], a[0], b0, b1);
                mma_tf32(acc[1][nf], a[1], b0, b1);
            }
        }
        __syncthreads();
    }

#pragma unroll
    for (int mf = 0; mf < 2; mf++) {
#pragma unroll
        for (int nf = 0; nf < 8; nf++) {
            int row = rowBase + wm * 32 + mf * 16 + (lane >> 2);
            int col = wn * 64 + nf * 8 + (lane & 3) * 2;
            if (row < Mtot) {
                float2 v0 = {acc[mf][nf][0], acc[mf][nf][1]};
                *(float2*)&C[(size_t)row * 128 + col] = v0;
                if (wn == 0)
                    *(__half2*)&Ch[(size_t)row * 64 + col] = __floats2half2_rn(v0.x, v0.y);
            }
            if (row + 8 < Mtot) {
                float2 v1 = {acc[mf][nf][2], acc[mf][nf][3]};
                *(float2*)&C[(size_t)(row + 8) * 128 + col] = v1;
                if (wn == 0)
                    *(__half2*)&Ch[(size_t)(row + 8) * 64 + col] = __floats2half2_rn(v1.x, v1.y);
            }
        }
    }
}

// ---------------- layer-1 aggregate + h + attention scalars ----------------
// 16 threads/node, thread q owns features q*4..q*4+3; gathers fp16 xn rows (128B).
__global__ void aggr_kernel(const int* __restrict__ nbr1, const int* __restrict__ nbr2,
                            const float* __restrict__ watt) {
    int t = threadIdx.x;
    int nodeLocal = t >> 4;
    int q = t & 15;
    int node = blockIdx.x * 16 + nodeLocal;
    int g = node >= NN;
    int i = g ? node - NN : node;
    const int* nbr = g ? nbr2 : nbr1;
    size_t gbase = (size_t)g * NN;

    int nid = __ldg(&nbr[i * 16 + q]);

    float4 s = {0.f, 0.f, 0.f, 0.f};
#pragma unroll
    for (int k = 0; k < 16; k++) {
        int j = __shfl_sync(0xffffffffu, nid, k, 16);
        uint2 raw = *(const uint2*)&g_zn_h[(gbase + j) * 64 + q * 4];
        float2 lo = __half22float2(*(__half2*)&raw.x);
        float2 hi = __half22float2(*(__half2*)&raw.y);
        s.x += lo.x; s.y += lo.y; s.z += hi.x; s.w += hi.y;
    }
    s.x *= (1.f / 16.f); s.y *= (1.f / 16.f); s.z *= (1.f / 16.f); s.w *= (1.f / 16.f);

    // half-rounded aggregate (consistent with attn's f16 Gram)
    __half2 h0 = __floats2half2_rn(s.x, s.y);
    __half2 h1 = __floats2half2_rn(s.z, s.w);
    uint2 packed = {*(uint32_t*)&h0, *(uint32_t*)&h1};
    *(uint2*)&g_aggr_h[(size_t)node * 64 + q * 4] = packed;
    float2 r0 = __half22float2(h0);
    float2 r1 = __half22float2(h1);

    float4 xs = *(const float4*)&g_z[(size_t)node * 128 + 64 + q * 4];
    float4 hx = {sigmoidf_(xs.x), sigmoidf_(xs.y), sigmoidf_(xs.z), sigmoidf_(xs.w)};
    float4 ha = {sigmoidf_(s.x), sigmoidf_(s.y), sigmoidf_(s.z), sigmoidf_(s.w)};
    *(float4*)&g_h[(size_t)node * 128 + q * 4] = hx;
    *(float4*)&g_h[(size_t)node * 128 + 64 + q * 4] = ha;

    float4 w0 = *(const float4*)&watt[q * 4];
    float4 w1 = *(const float4*)&watt[64 + q * 4];
    float p0 = s.x * w0.x + s.y * w0.y + s.z * w0.z + s.w * w0.w;
    float p1 = s.x * w1.x + s.y * w1.y + s.z * w1.z + s.w * w1.w;
    float p2 = r0.x * r0.x + r0.y * r0.y + r1.x * r1.x + r1.y * r1.y;
#pragma unroll
    for (int o = 8; o; o >>= 1) {
        p0 += __shfl_xor_sync(0xffffffffu, p0, o);
        p1 += __shfl_xor_sync(0xffffffffu, p1, o);
        p2 += __shfl_xor_sync(0xffffffffu, p2, o);
    }
    if (q == 0) {
        g_si[node] = p0;
        g_sj[node] = p1;
        g_nsq[node] = p2;
    }
}

// ---------------- cross-attn + self-attn via f16 tensor-core Gram ----------------
// One warp per node. Tiles: 16 rows x 64 halves, row stride 36 words (conflict-free:
// word = 36*row + kq -> bank 4*row + kq distinct over the 32 lanes of a fragment load).
#define ATW 36
__global__ void attn_kernel(const int* __restrict__ nbr1, const int* __restrict__ nbr2) {
    __shared__ uint32_t sm[4][2 * 16 * ATW];   // per warp: a1[16][36w] | a2[16][36w]
    int warp = threadIdx.x >> 5;
    int lane = threadIdx.x & 31;
    int i = blockIdx.x * 4 + warp;
    uint32_t* a1s = sm[warp];
    uint32_t* a2s = sm[warp] + 16 * ATW;

    int nid;
    if (lane < 16) nid = nbr1[i * 16 + lane];
    else           nid = nbr2[i * 16 + (lane - 16)];

    // ---- gather 32 rows x 128B (fp16), 8 iterations of 32x16B ----
#pragma unroll
    for (int it = 0; it < 8; it++) {
        int idx = it * 32 + lane;          // 0..255
        int arr = idx >> 7;                // 0 = a1, 1 = a2
        int local = idx & 127;
        int row = local >> 3, d4 = local & 7;
        int j = __shfl_sync(0xffffffffu, nid, arr * 16 + row);
        uint4 v = *((const uint4*)g_aggr_h + ((size_t)(arr ? NN : 0) + j) * 8 + d4);
        *(uint4*)&sm[warp][arr * 16 * ATW + row * ATW + d4 * 4] = v;
    }
    float myNsq = (lane < 16) ? g_nsq[nid] : g_nsq[NN + nid];
    __syncwarp();

    // ---- Gram via mma.m16n8k16.f16: 2 n-tiles x 4 k-steps ----
    int rq = lane >> 2;                   // 0..7
    int kq = lane & 3;                    // 0..3
    float acc[2][4];
#pragma unroll
    for (int nt = 0; nt < 2; nt++)
#pragma unroll
        for (int c = 0; c < 4; c++) acc[nt][c] = 0.f;

#pragma unroll
    for (int ks = 0; ks < 4; ks++) {
        int kb = ks * 8;                  // word offset (16 halves per step)
        uint32_t a[4];
        a[0] = a1s[rq * ATW + kb + kq];
        a[1] = a1s[(rq + 8) * ATW + kb + kq];
        a[2] = a1s[rq * ATW + kb + kq + 4];
        a[3] = a1s[(rq + 8) * ATW + kb + kq + 4];
#pragma unroll
        for (int nt = 0; nt < 2; nt++) {
            uint32_t b0 = a2s[(nt * 8 + rq) * ATW + kb + kq];
            uint32_t b1 = a2s[(nt * 8 + rq) * ATW + kb + kq + 4];
            mma_f16(acc[nt], a, b0, b1);
        }
    }

    // ---- sims + marginals; C frag: rows {rq, rq+8}, cols nt*8 + 2kq + {0,1} ----
    float nsqK0 = __shfl_sync(0xffffffffu, myNsq, rq);
    float nsqK1 = __shfl_sync(0xffffffffu, myNsq, rq + 8);
    float rp0 = 0.f, rp1 = 0.f;
    float cp[2][2];
#pragma unroll
    for (int nt = 0; nt < 2; nt++) {
        float nsqL0 = __shfl_sync(0xffffffffu, myNsq, 16 + nt * 8 + 2 * kq);
        float nsqL1 = __shfl_sync(0xffffffffu, myNsq, 16 + nt * 8 + 2 * kq + 1);
        float s00 = __expf(-sqrtf(fmaxf(nsqK0 + nsqL0 - 2.f * acc[nt][0], 1e-12f)));
        float s01 = __expf(-sqrtf(fmaxf(nsqK0 + nsqL1 - 2.f * acc[nt][1], 1e-12f)));
        float s10 = __expf(-sqrtf(fmaxf(nsqK1 + nsqL0 - 2.f * acc[nt][2], 1e-12f)));
        float s11 = __expf(-sqrtf(fmaxf(nsqK1 + nsqL1 - 2.f * acc[nt][3], 1e-12f)));
        rp0 += s00 + s01;
        rp1 += s10 + s11;
        cp[nt][0] = s00 + s10;
        cp[nt][1] = s01 + s11;
    }
    float tot = rp0 + rp1;
#pragma unroll
    for (int o = 16; o; o >>= 1) tot += __shfl_xor_sync(0xffffffffu, tot, o);

    rp0 += __shfl_xor_sync(0xffffffffu, rp0, 1);
    rp1 += __shfl_xor_sync(0xffffffffu, rp1, 1);
    rp0 += __shfl_xor_sync(0xffffffffu, rp0, 2);
    rp1 += __shfl_xor_sync(0xffffffffu, rp1, 2);
#pragma unroll
    for (int o = 4; o <= 16; o <<= 1) {
        cp[0][0] += __shfl_xor_sync(0xffffffffu, cp[0][0], o);
        cp[0][1] += __shfl_xor_sync(0xffffffffu, cp[0][1], o);
        cp[1][0] += __shfl_xor_sync(0xffffffffu, cp[1][0], o);
        cp[1][1] += __shfl_xor_sync(0xffffffffu, cp[1][1], o);
    }

    int kl = lane & 15;
    float r0v = __shfl_sync(0xffffffffu, rp0, 4 * (kl & 7));
    float r1v = __shfl_sync(0xffffffffu, rp1, 4 * (kl & 7));
    float rowval = (kl < 8) ? r0v : r1v;
    int srcC = (kl & 7) >> 1;
    float c00 = __shfl_sync(0xffffffffu, cp[0][0], srcC);
    float c01 = __shfl_sync(0xffffffffu, cp[0][1], srcC);
    float c10 = __shfl_sync(0xffffffffu, cp[1][0], srcC);
    float c11 = __shfl_sync(0xffffffffu, cp[1][1], srcC);
    float colval = (kl >> 3) ? ((kl & 1) ? c11 : c10) : ((kl & 1) ? c01 : c00);

    float cross = ((lane < 16) ? rowval : colval) / tot;

    float sii = (lane < 16) ? g_si[i] : g_si[NN + i];
    float sjv = (lane < 16) ? g_sj[nid] : g_sj[NN + nid];
    float zz = sii + sjv;
    float lr = (zz >= 0.f) ? zz : 0.01f * zz;
    float e = __expf(lr);
    float esum = e;
#pragma unroll
    for (int o = 8; o; o >>= 1) esum += __shfl_xor_sync(0xffffffffu, esum, o);

    float nrm = cross * (e / esum);
    if (lane < 16) g_norm[(size_t)i * 16 + lane] = nrm;
    else           g_norm[(size_t)(NN + i) * 16 + (lane - 16)] = nrm;
}

// ---------------- final weighted aggregate + sigmoid -> output ----------------
__global__ void out_kernel(const int* __restrict__ nbr1, const int* __restrict__ nbr2,
                           float* __restrict__ out) {
    int t = threadIdx.x;
    int nodeLocal = t >> 4;
    int q = t & 15;
    int node = blockIdx.x * 16 + nodeLocal;
    int g = node >= NN;
    int i = g ? node - NN : node;
    const int* nbr = g ? nbr2 : nbr1;
    size_t gbase = (size_t)g * NN;

    int nid = __ldg(&nbr[i * 16 + q]);
    float wq = g_norm[(size_t)node * 16 + q];

    float4 s = {0.f, 0.f, 0.f, 0.f};
#pragma unroll
    for (int k = 0; k < 16; k++) {
        int j = __shfl_sync(0xffffffffu, nid, k, 16);
        float w = __shfl_sync(0xffffffffu, wq, k, 16);
        uint2 raw = *(const uint2*)&g_yn_h[(gbase + j) * 64 + q * 4];
        float2 lo = __half22float2(*(__half2*)&raw.x);
        float2 hi = __half22float2(*(__half2*)&raw.y);
        s.x += w * lo.x; s.y += w * lo.y; s.z += w * hi.x; s.w += w * hi.y;
    }

    float4 ys = *(const float4*)&g_y[(size_t)node * 128 + 64 + q * 4];
    float4 o0 = {sigmoidf_(ys.x), sigmoidf_(ys.y), sigmoidf_(ys.z), sigmoidf_(ys.w)};
    float4 o1 = {sigmoidf_(s.x), sigmoidf_(s.y), sigmoidf_(s.z), sigmoidf_(s.w)};
    *(float4*)&out[(size_t)node * 128 + q * 4] = o0;
    *(float4*)&out[(size_t)node * 128 + 64 + q * 4] = o1;
}

// ---------------- launch ----------------
extern "C" void kernel_launch(void* const* d_in, const int* in_sizes, int n_in,
                              void* d_out, int out_size) {
    const float* x1   = (const float*)d_in[0];
    const float* x2   = (const float*)d_in[1];
    const int*   nbr1 = (const int*)d_in[2];
    const int*   nbr2 = (const int*)d_in[3];
    const float* We1  = (const float*)d_in[4];
    const float* Ws1  = (const float*)d_in[5];
    const float* We2  = (const float*)d_in[6];
    const float* Ws2  = (const float*)d_in[7];
    const float* watt = (const float*)d_in[8];
    float* out = (float*)d_out;

    cudaFuncSetAttribute(gemm_tc, cudaFuncAttributeMaxDynamicSharedMemorySize, GEMM_SMEM);

    pack_B_kernel<<<64, 256>>>(We1, Ws1, We2, Ws2);

    int gb = (2 * NN + 127) / 128;
    gemm_tc<<<gb, 256, GEMM_SMEM>>>(x1, x2, 1);

    aggr_kernel<<<(2 * NN) / 16, 256>>>(nbr1, nbr2, watt);
    attn_kernel<<<NN / 4, 128>>>(nbr1, nbr2);

    gemm_tc<<<gb, 256, GEMM_SMEM>>>(x1, x2, 2);

    out_kernel<<<(2 * NN) / 16, 256>>>(nbr1, nbr2, out);
}

// round 6
// speedup vs baseline: 3.8394x; 1.1615x over previous
#include <cuda_runtime.h>
#include <cuda_fp16.h>
#include <cstdint>

#define NN 50000
#define KNBR 16

// ---------------- scratch (device globals; no runtime allocation) ----------------
__device__ __align__(16) __half g_B1h[128 * 128];     // [n][k] halves: W1 = [We1|Ws1]^T
__device__ __align__(16) __half g_B2h[128 * 128];     // [n][k] halves
__device__ __align__(16) float  g_zs[2 * NN * 64];    // xs (self transform), fp32
__device__ __align__(16) float  g_ys[2 * NN * 64];    // ys, fp32
__device__ __align__(16) __half g_zn_h[2 * NN * 64];  // xn fp16 (gather operand)
__device__ __align__(16) __half g_yn_h[2 * NN * 64];  // yn fp16 (gather operand)
__device__ __align__(16) __half g_h_h[2 * NN * 128];  // h = sigmoid(cat(xs,aggr)), fp16
__device__ __align__(16) __half g_aggr_h[2 * NN * 64];
__device__ float g_si[2 * NN];
__device__ float g_sj[2 * NN];
__device__ float g_nsq[2 * NN];
__device__ float g_norm[2 * NN * KNBR];

__device__ __forceinline__ float sigmoidf_(float x) { return 1.f / (1.f + __expf(-x)); }

__device__ __forceinline__ void mma_f16(float* d, const uint32_t* a, uint32_t b0, uint32_t b1) {
    asm volatile(
        "mma.sync.aligned.m16n8k16.row.col.f32.f16.f16.f32 "
        "{%0,%1,%2,%3}, {%4,%5,%6,%7}, {%8,%9}, {%0,%1,%2,%3};"
        : "+f"(d[0]), "+f"(d[1]), "+f"(d[2]), "+f"(d[3])
        : "r"(a[0]), "r"(a[1]), "r"(a[2]), "r"(a[3]), "r"(b0), "r"(b1));
}

__device__ __forceinline__ void ldm_x4(uint32_t* r, const uint32_t* p) {
    uint32_t addr = (uint32_t)__cvta_generic_to_shared(p);
    asm volatile("ldmatrix.sync.aligned.m8n8.x4.shared.b16 {%0,%1,%2,%3}, [%4];"
                 : "=r"(r[0]), "=r"(r[1]), "=r"(r[2]), "=r"(r[3]) : "r"(addr));
}

// ---------------- pack W -> [n][k] fp16 ----------------
__global__ void pack_B_kernel(const float* __restrict__ We1, const float* __restrict__ Ws1,
                              const float* __restrict__ We2, const float* __restrict__ Ws2) {
    int idx = blockIdx.x * blockDim.x + threadIdx.x;
    if (idx >= 128 * 128) return;
    int n = idx >> 7, k = idx & 127;
    float v1 = (n < 64) ? We1[k * 64 + n] : Ws1[k * 64 + (n - 64)];
    float v2 = (n < 64) ? We2[k * 64 + n] : Ws2[k * 64 + (n - 64)];
    g_B1h[idx] = __float2half_rn(v1);
    g_B2h[idx] = __float2half_rn(v2);
}

// ---------------- fp16 tensor-core GEMM: C[M,128] = A[M,128] @ B[128,128] ----------------
// Full K resident; 256 threads = 8 warps (4m x 2n); warp tile 32x64.
// Smem rows stride AG=68 words; ldmatrix fragment loads, conflict-free.
#define AG 68
#define GEMM_SMEM (2 * 128 * AG * 4)

__global__ void gemm_tc(const float* __restrict__ x1, const float* __restrict__ x2, int layer) {
    extern __shared__ uint32_t smg[];
    uint32_t* As = smg;                 // [128 rows][AG words]
    uint32_t* Bs = smg + 128 * AG;      // [128 n][AG words]

    const int Mtot = 2 * NN;
    const __half* __restrict__ Bg = (layer == 1) ? g_B1h : g_B2h;
    float*  __restrict__ Cs = (layer == 1) ? g_zs : g_ys;
    __half* __restrict__ Ch = (layer == 1) ? g_zn_h : g_yn_h;

    int tid = threadIdx.x;
    int rowBase = blockIdx.x * 128;

    // ---- load A tile ----
    if (layer == 1) {
#pragma unroll
        for (int it = 0; it < 16; it++) {
            int row = (tid >> 5) + it * 8;
            int f4 = tid & 31;
            int grow = rowBase + row;
            float4 v = {0.f, 0.f, 0.f, 0.f};
            if (grow < Mtot) {
                const float* src = (grow < NN) ? (x1 + (size_t)grow * 128)
                                               : (x2 + (size_t)(grow - NN) * 128);
                v = *(const float4*)(src + f4 * 4);
            }
            __half2 w0 = __floats2half2_rn(v.x, v.y);
            __half2 w1 = __floats2half2_rn(v.z, v.w);
            uint2 w = {*(uint32_t*)&w0, *(uint32_t*)&w1};
            *(uint2*)&As[row * AG + f4 * 2] = w;
        }
    } else {
#pragma unroll
        for (int it = 0; it < 8; it++) {
            int row = (tid >> 4) + it * 16;
            int c = tid & 15;
            int grow = rowBase + row;
            uint4 v = {0, 0, 0, 0};
            if (grow < Mtot) v = *(const uint4*)&g_h_h[(size_t)grow * 128 + c * 8];
            *(uint4*)&As[row * AG + c * 4] = v;
        }
    }
    // ---- load B tile [n][k] ----
#pragma unroll
    for (int it = 0; it < 8; it++) {
        int n = (tid >> 4) + it * 16;
        int c = tid & 15;
        uint4 v = *(const uint4*)&Bg[(size_t)n * 128 + c * 8];
        *(uint4*)&Bs[n * AG + c * 4] = v;
    }
    __syncthreads();

    int lane = tid & 31;
    int wm = (tid >> 5) & 3;
    int wn = tid >> 7;
    int lr = lane & 7, lg = lane >> 3;

    float acc[2][8][4];
#pragma unroll
    for (int mf = 0; mf < 2; mf++)
#pragma unroll
        for (int nf = 0; nf < 8; nf++)
#pragma unroll
            for (int c = 0; c < 4; c++) acc[mf][nf][c] = 0.f;

#pragma unroll
    for (int ks = 0; ks < 8; ks++) {
        int kb = ks * 8;
        uint32_t a[2][4];
#pragma unroll
        for (int mf = 0; mf < 2; mf++) {
            int row = wm * 32 + mf * 16 + lr + (lg & 1) * 8;
            int word = kb + (lg >> 1) * 4;
            ldm_x4(a[mf], &As[row * AG + word]);
        }
        uint32_t b[8][2];
#pragma unroll
        for (int p = 0; p < 4; p++) {
            int n = wn * 64 + p * 16 + lr + (lg >> 1) * 8;
            int word = kb + (lg & 1) * 4;
            ldm_x4(&b[2 * p][0], &Bs[n * AG + word]);
        }
#pragma unroll
        for (int mf = 0; mf < 2; mf++)
#pragma unroll
            for (int nf = 0; nf < 8; nf++)
                mma_f16(acc[mf][nf], a[mf], b[nf][0], b[nf][1]);
    }

    // ---- epilogue: cols<64 -> fp16 (gather operand); cols>=64 -> fp32 self buffer ----
    int rq = lane >> 2, kq = lane & 3;
#pragma unroll
    for (int mf = 0; mf < 2; mf++) {
#pragma unroll
        for (int nf = 0; nf < 8; nf++) {
            int row = rowBase + wm * 32 + mf * 16 + rq;
            int col = nf * 8 + kq * 2;            // 0..63 within the wn half
            if (wn == 0) {
                if (row < Mtot) {
                    __half2 h = __floats2half2_rn(acc[mf][nf][0], acc[mf][nf][1]);
                    *(uint32_t*)&Ch[(size_t)row * 64 + col] = *(uint32_t*)&h;
                }
                if (row + 8 < Mtot) {
                    __half2 h = __floats2half2_rn(acc[mf][nf][2], acc[mf][nf][3]);
                    *(uint32_t*)&Ch[(size_t)(row + 8) * 64 + col] = *(uint32_t*)&h;
                }
            } else {
                if (row < Mtot) {
                    float2 v = {acc[mf][nf][0], acc[mf][nf][1]};
                    *(float2*)&Cs[(size_t)row * 64 + col] = v;
                }
                if (row + 8 < Mtot) {
                    float2 v = {acc[mf][nf][2], acc[mf][nf][3]};
                    *(float2*)&Cs[(size_t)(row + 8) * 64 + col] = v;
                }
            }
        }
    }
}

// ---------------- layer-1 aggregate + h + attention scalars ----------------
__global__ void aggr_kernel(const int* __restrict__ nbr1, const int* __restrict__ nbr2,
                            const float* __restrict__ watt) {
    int t = threadIdx.x;
    int nodeLocal = t >> 4;
    int q = t & 15;
    int node = blockIdx.x * 16 + nodeLocal;
    int g = node >= NN;
    int i = g ? node - NN : node;
    const int* nbr = g ? nbr2 : nbr1;
    size_t gbase = (size_t)g * NN;

    int nid = __ldg(&nbr[i * 16 + q]);

    float4 s = {0.f, 0.f, 0.f, 0.f};
#pragma unroll
    for (int k = 0; k < 16; k++) {
        int j = __shfl_sync(0xffffffffu, nid, k, 16);
        uint2 raw = *(const uint2*)&g_zn_h[(gbase + j) * 64 + q * 4];
        float2 lo = __half22float2(*(__half2*)&raw.x);
        float2 hi = __half22float2(*(__half2*)&raw.y);
        s.x += lo.x; s.y += lo.y; s.z += hi.x; s.w += hi.y;
    }
    s.x *= (1.f / 16.f); s.y *= (1.f / 16.f); s.z *= (1.f / 16.f); s.w *= (1.f / 16.f);

    __half2 h0 = __floats2half2_rn(s.x, s.y);
    __half2 h1 = __floats2half2_rn(s.z, s.w);
    uint2 packed = {*(uint32_t*)&h0, *(uint32_t*)&h1};
    *(uint2*)&g_aggr_h[(size_t)node * 64 + q * 4] = packed;
    float2 r0 = __half22float2(h0);
    float2 r1 = __half22float2(h1);

    float4 xs = *(const float4*)&g_zs[(size_t)node * 64 + q * 4];
    __half2 hx0 = __floats2half2_rn(sigmoidf_(xs.x), sigmoidf_(xs.y));
    __half2 hx1 = __floats2half2_rn(sigmoidf_(xs.z), sigmoidf_(xs.w));
    __half2 ha0 = __floats2half2_rn(sigmoidf_(s.x), sigmoidf_(s.y));
    __half2 ha1 = __floats2half2_rn(sigmoidf_(s.z), sigmoidf_(s.w));
    uint2 px = {*(uint32_t*)&hx0, *(uint32_t*)&hx1};
    uint2 pa = {*(uint32_t*)&ha0, *(uint32_t*)&ha1};
    *(uint2*)&g_h_h[(size_t)node * 128 + q * 4] = px;
    *(uint2*)&g_h_h[(size_t)node * 128 + 64 + q * 4] = pa;

    float4 w0 = *(const float4*)&watt[q * 4];
    float4 w1 = *(const float4*)&watt[64 + q * 4];
    float p0 = s.x * w0.x + s.y * w0.y + s.z * w0.z + s.w * w0.w;
    float p1 = s.x * w1.x + s.y * w1.y + s.z * w1.z + s.w * w1.w;
    float p2 = r0.x * r0.x + r0.y * r0.y + r1.x * r1.x + r1.y * r1.y;
#pragma unroll
    for (int o = 8; o; o >>= 1) {
        p0 += __shfl_xor_sync(0xffffffffu, p0, o);
        p1 += __shfl_xor_sync(0xffffffffu, p1, o);
        p2 += __shfl_xor_sync(0xffffffffu, p2, o);
    }
    if (q == 0) {
        g_si[node] = p0;
        g_sj[node] = p1;
        g_nsq[node] = p2;
    }
}

// ---------------- cross-attn + self-attn via f16 tensor-core Gram ----------------
#define ATW 36
__global__ void attn_kernel(const int* __restrict__ nbr1, const int* __restrict__ nbr2) {
    __shared__ uint32_t sm[4][2 * 16 * ATW];
    int warp = threadIdx.x >> 5;
    int lane = threadIdx.x & 31;
    int i = blockIdx.x * 4 + warp;
    uint32_t* a1s = sm[warp];
    uint32_t* a2s = sm[warp] + 16 * ATW;

    int nid;
    if (lane < 16) nid = nbr1[i * 16 + lane];
    else           nid = nbr2[i * 16 + (lane - 16)];

#pragma unroll
    for (int it = 0; it < 8; it++) {
        int idx = it * 32 + lane;
        int arr = idx >> 7;
        int local = idx & 127;
        int row = local >> 3, d4 = local & 7;
        int j = __shfl_sync(0xffffffffu, nid, arr * 16 + row);
        uint4 v = *((const uint4*)g_aggr_h + ((size_t)(arr ? NN : 0) + j) * 8 + d4);
        *(uint4*)&sm[warp][arr * 16 * ATW + row * ATW + d4 * 4] = v;
    }
    float myNsq = (lane < 16) ? g_nsq[nid] : g_nsq[NN + nid];
    __syncwarp();

    int rq = lane >> 2;
    int kq = lane & 3;
    int lr = lane & 7, lg = lane >> 3;
    float acc[2][4];
#pragma unroll
    for (int nt = 0; nt < 2; nt++)
#pragma unroll
        for (int c = 0; c < 4; c++) acc[nt][c] = 0.f;

#pragma unroll
    for (int ks = 0; ks < 4; ks++) {
        int kb = ks * 8;
        uint32_t a[4], b[2][2];
        ldm_x4(a, &a1s[(lr + (lg & 1) * 8) * ATW + kb + (lg >> 1) * 4]);
        ldm_x4(&b[0][0], &a2s[(lr + (lg >> 1) * 8) * ATW + kb + (lg & 1) * 4]);
        mma_f16(acc[0], a, b[0][0], b[0][1]);
        mma_f16(acc[1], a, b[1][0], b[1][1]);
    }

    float nsqK0 = __shfl_sync(0xffffffffu, myNsq, rq);
    float nsqK1 = __shfl_sync(0xffffffffu, myNsq, rq + 8);
    float rp0 = 0.f, rp1 = 0.f;
    float cp[2][2];
#pragma unroll
    for (int nt = 0; nt < 2; nt++) {
        float nsqL0 = __shfl_sync(0xffffffffu, myNsq, 16 + nt * 8 + 2 * kq);
        float nsqL1 = __shfl_sync(0xffffffffu, myNsq, 16 + nt * 8 + 2 * kq + 1);
        float s00 = __expf(-sqrtf(fmaxf(nsqK0 + nsqL0 - 2.f * acc[nt][0], 1e-12f)));
        float s01 = __expf(-sqrtf(fmaxf(nsqK0 + nsqL1 - 2.f * acc[nt][1], 1e-12f)));
        float s10 = __expf(-sqrtf(fmaxf(nsqK1 + nsqL0 - 2.f * acc[nt][2], 1e-12f)));
        float s11 = __expf(-sqrtf(fmaxf(nsqK1 + nsqL1 - 2.f * acc[nt][3], 1e-12f)));
        rp0 += s00 + s01;
        rp1 += s10 + s11;
        cp[nt][0] = s00 + s10;
        cp[nt][1] = s01 + s11;
    }
    float tot = rp0 + rp1;
#pragma unroll
    for (int o = 16; o; o >>= 1) tot += __shfl_xor_sync(0xffffffffu, tot, o);

    rp0 += __shfl_xor_sync(0xffffffffu, rp0, 1);
    rp1 += __shfl_xor_sync(0xffffffffu, rp1, 1);
    rp0 += __shfl_xor_sync(0xffffffffu, rp0, 2);
    rp1 += __shfl_xor_sync(0xffffffffu, rp1, 2);
#pragma unroll
    for (int o = 4; o <= 16; o <<= 1) {
        cp[0][0] += __shfl_xor_sync(0xffffffffu, cp[0][0], o);
        cp[0][1] += __shfl_xor_sync(0xffffffffu, cp[0][1], o);
        cp[1][0] += __shfl_xor_sync(0xffffffffu, cp[1][0], o);
        cp[1][1] += __shfl_xor_sync(0xffffffffu, cp[1][1], o);
    }

    int kl = lane & 15;
    float r0v = __shfl_sync(0xffffffffu, rp0, 4 * (kl & 7));
    float r1v = __shfl_sync(0xffffffffu, rp1, 4 * (kl & 7));
    float rowval = (kl < 8) ? r0v : r1v;
    int srcC = (kl & 7) >> 1;
    float c00 = __shfl_sync(0xffffffffu, cp[0][0], srcC);
    float c01 = __shfl_sync(0xffffffffu, cp[0][1], srcC);
    float c10 = __shfl_sync(0xffffffffu, cp[1][0], srcC);
    float c11 = __shfl_sync(0xffffffffu, cp[1][1], srcC);
    float colval = (kl >> 3) ? ((kl & 1) ? c11 : c10) : ((kl & 1) ? c01 : c00);

    float cross = ((lane < 16) ? rowval : colval) / tot;

    float sii = (lane < 16) ? g_si[i] : g_si[NN + i];
    float sjv = (lane < 16) ? g_sj[nid] : g_sj[NN + nid];
    float zz = sii + sjv;
    float lr2 = (zz >= 0.f) ? zz : 0.01f * zz;
    float e = __expf(lr2);
    float esum = e;
#pragma unroll
    for (int o = 8; o; o >>= 1) esum += __shfl_xor_sync(0xffffffffu, esum, o);

    float nrm = cross * (e / esum);
    if (lane < 16) g_norm[(size_t)i * 16 + lane] = nrm;
    else           g_norm[(size_t)(NN + i) * 16 + (lane - 16)] = nrm;
}

// ---------------- final weighted aggregate + sigmoid -> output ----------------
__global__ void out_kernel(const int* __restrict__ nbr1, const int* __restrict__ nbr2,
                           float* __restrict__ out) {
    int t = threadIdx.x;
    int nodeLocal = t >> 4;
    int q = t & 15;
    int node = blockIdx.x * 16 + nodeLocal;
    int g = node >= NN;
    int i = g ? node - NN : node;
    const int* nbr = g ? nbr2 : nbr1;
    size_t gbase = (size_t)g * NN;

    int nid = __ldg(&nbr[i * 16 + q]);
    float wq = g_norm[(size_t)node * 16 + q];

    float4 s = {0.f, 0.f, 0.f, 0.f};
#pragma unroll
    for (int k = 0; k < 16; k++) {
        int j = __shfl_sync(0xffffffffu, nid, k, 16);
        float w = __shfl_sync(0xffffffffu, wq, k, 16);
        uint2 raw = *(const uint2*)&g_yn_h[(gbase + j) * 64 + q * 4];
        float2 lo = __half22float2(*(__half2*)&raw.x);
        float2 hi = __half22float2(*(__half2*)&raw.y);
        s.x += w * lo.x; s.y += w * lo.y; s.z += w * hi.x; s.w += w * hi.y;
    }

    float4 ys = *(const float4*)&g_ys[(size_t)node * 64 + q * 4];
    float4 o0 = {sigmoidf_(ys.x), sigmoidf_(ys.y), sigmoidf_(ys.z), sigmoidf_(ys.w)};
    float4 o1 = {sigmoidf_(s.x), sigmoidf_(s.y), sigmoidf_(s.z), sigmoidf_(s.w)};
    *(float4*)&out[(size_t)node * 128 + q * 4] = o0;
    *(float4*)&out[(size_t)node * 128 + 64 + q * 4] = o1;
}

// ---------------- launch ----------------
extern "C" void kernel_launch(void* const* d_in, const int* in_sizes, int n_in,
                              void* d_out, int out_size) {
    const float* x1   = (const float*)d_in[0];
    const float* x2   = (const float*)d_in[1];
    const int*   nbr1 = (const int*)d_in[2];
    const int*   nbr2 = (const int*)d_in[3];
    const float* We1  = (const float*)d_in[4];
    const float* Ws1  = (const float*)d_in[5];
    const float* We2  = (const float*)d_in[6];
    const float* Ws2  = (const float*)d_in[7];
    const float* watt = (const float*)d_in[8];
    float* out = (float*)d_out;

    // one-time side stream + events (resource init, not work; deterministic after init)
    static cudaStream_t s_side = 0;
    static cudaEvent_t evF = 0, evJ = 0;
    static int smode = 0;
    if (smode == 0) {
        if (cudaStreamCreateWithFlags(&s_side, cudaStreamNonBlocking) == cudaSuccess &&
            cudaEventCreateWithFlags(&evF, cudaEventDisableTiming) == cudaSuccess &&
            cudaEventCreateWithFlags(&evJ, cudaEventDisableTiming) == cudaSuccess)
            smode = 1;
        else
            smode = -1;
    }

    cudaFuncSetAttribute(gemm_tc, cudaFuncAttributeMaxDynamicSharedMemorySize, GEMM_SMEM);

    pack_B_kernel<<<64, 256>>>(We1, Ws1, We2, Ws2);

    int gb = (2 * NN + 127) / 128;
    gemm_tc<<<gb, 256, GEMM_SMEM>>>(x1, x2, 1);

    aggr_kernel<<<(2 * NN) / 16, 256>>>(nbr1, nbr2, watt);

    if (smode == 1) {
        // fork: attn on side stream, gemm2 on main (independent: gemm2 needs only g_h_h)
        cudaEventRecord(evF, 0);
        cudaStreamWaitEvent(s_side, evF, 0);
        attn_kernel<<<NN / 4, 128, 0, s_side>>>(nbr1, nbr2);
        cudaEventRecord(evJ, s_side);
        gemm_tc<<<gb, 256, GEMM_SMEM>>>(x1, x2, 2);
        cudaStreamWaitEvent(0, evJ, 0);
    } else {
        attn_kernel<<<NN / 4, 128>>>(nbr1, nbr2);
        gemm_tc<<<gb, 256, GEMM_SMEM>>>(x1, x2, 2);
    }

    out_kernel<<<(2 * NN) / 16, 256>>>(nbr1, nbr2, out);
}